// round 1
// baseline (speedup 1.0000x reference)
#include <cuda_runtime.h>

// Based-style quadratic linear attention.
// a_ts = 1 + S + 0.5*S^2, S = (q_t * d^-0.5) . k_s
// out_t = (sum_{s<=t} a_ts v_s) / (sum_{s<=t} a_ts + 1e-6)
// Chunked: per-chunk states {sum_v, sum_k, sum_kk, sum_kv, sum_kkv},
// exclusive prefix over chunks, then per-chunk output pass.

#define BH   32      // b*h
#define NCH  16      // chunks per sequence
#define CS   256     // chunk size
#define D    16
#define DV   64
#define DV4  16      // DV/4
#define SEQ  4096

// per-(bh,chunk) state layout (floats)
#define ST_KKV  0        // 16*16*64 = 16384
#define ST_KV   16384    // 16*64    = 1024
#define ST_KK   17408    // 16*16    = 256
#define ST_K    17664    // 16
#define ST_V    17680    // 64
#define ST_SIZE 17744

__device__ float g_state[(size_t)BH * NCH * ST_SIZE];   // ~36.3 MB scratch

// ---------------------------------------------------------------------------
// K1: per-chunk local state sums. grid (BH, NCH), 256 threads.
// thread = (d = tid&15, e = tid>>4); owns kkv[d][e][0:64], kv[d][4e:4e+4], kk[d][e].
// All compute-loop smem reads are (near-)broadcasts -> conflict free.
// ---------------------------------------------------------------------------
__global__ __launch_bounds__(256) void k1_chunk_sums(
    const float* __restrict__ k, const float* __restrict__ v)
{
    extern __shared__ float sm[];
    float*  sk = sm;                        // CS*D floats
    float4* sv = (float4*)(sm + CS * D);    // CS*DV4 float4s

    const int bh = blockIdx.x, ch = blockIdx.y, tid = threadIdx.x;
    const float*  kb = k + ((size_t)bh * SEQ + (size_t)ch * CS) * D;
    const float4* vb = (const float4*)(v + ((size_t)bh * SEQ + (size_t)ch * CS) * DV);

    for (int i = tid; i < CS * D;   i += 256) sk[i] = kb[i];
    for (int i = tid; i < CS * DV4; i += 256) sv[i] = vb[i];
    __syncthreads();

    const int d = tid & 15, e = tid >> 4;

    float4 akkv[DV4];
#pragma unroll
    for (int j = 0; j < DV4; j++) akkv[j] = make_float4(0.f, 0.f, 0.f, 0.f);
    float4 akv = make_float4(0.f, 0.f, 0.f, 0.f);
    float4 av  = make_float4(0.f, 0.f, 0.f, 0.f);
    float  akk = 0.f, ak = 0.f;

    for (int c = 0; c < CS; c++) {
        const float kd = sk[c * D + d];
        const float ke = sk[c * D + e];
        const float w  = kd * ke;
        akk += w;
        if (e == 0) ak += kd;

        const float4* vr = sv + c * DV4;
        const float4  ve = vr[e];
        akv.x = fmaf(kd, ve.x, akv.x);
        akv.y = fmaf(kd, ve.y, akv.y);
        akv.z = fmaf(kd, ve.z, akv.z);
        akv.w = fmaf(kd, ve.w, akv.w);
        if (d == 0) { av.x += ve.x; av.y += ve.y; av.z += ve.z; av.w += ve.w; }

#pragma unroll
        for (int j = 0; j < DV4; j++) {
            const float4 vv = vr[j];
            akkv[j].x = fmaf(w, vv.x, akkv[j].x);
            akkv[j].y = fmaf(w, vv.y, akkv[j].y);
            akkv[j].z = fmaf(w, vv.z, akkv[j].z);
            akkv[j].w = fmaf(w, vv.w, akkv[j].w);
        }
    }

    float* st = g_state + (size_t)(bh * NCH + ch) * ST_SIZE;
    float4* kkvo = (float4*)(st + ST_KKV + (d * 16 + e) * DV);
#pragma unroll
    for (int j = 0; j < DV4; j++) kkvo[j] = akkv[j];
    ((float4*)(st + ST_KV))[d * DV4 + e] = akv;
    st[ST_KK + d * 16 + e] = akk;
    if (e == 0) st[ST_K + d] = ak;
    if (d == 0) ((float4*)(st + ST_V))[e] = av;
}

// ---------------------------------------------------------------------------
// K2: in-place exclusive prefix over the chunk axis. grid (BH, 18), 256 threads.
// ---------------------------------------------------------------------------
__global__ __launch_bounds__(256) void k2_prefix()
{
    const int bh = blockIdx.x;
    const int idx0   = blockIdx.y * blockDim.x + threadIdx.x;
    const int stride = gridDim.y * blockDim.x;
    float* base = g_state + (size_t)bh * NCH * ST_SIZE;
    for (int idx = idx0; idx < ST_SIZE; idx += stride) {
        float run = 0.f;
#pragma unroll
        for (int c = 0; c < NCH; c++) {
            float* p = base + (size_t)c * ST_SIZE + idx;
            const float t = *p;
            *p = run;
            run += t;
        }
    }
}

// ---------------------------------------------------------------------------
// K3: output pass. grid (BH, NCH), 256 threads = 256 query tokens.
// Warps remapped to token blocks {0,1,2,3,7,6,5,4} so paired warps on each
// SMSP carry a balanced causal-triangle load.
// ---------------------------------------------------------------------------
__global__ __launch_bounds__(256) void k3_output(
    const float* __restrict__ q, const float* __restrict__ k,
    const float* __restrict__ v, float* __restrict__ out)
{
    extern __shared__ float sm[];
    float* sk    = sm;                 // 4096
    float* sKKV  = sk + CS * D;        // 16384
    float* sTail = sKKV + 16384;       // 1360 contiguous: KV,KK,K,V
    float* sKV   = sTail;              // 1024
    float* sKK   = sKV + 1024;         // 256
    float* sKs   = sKK + 256;          // 16
    float* sVs   = sKs + 16;           // 64
    float4* sv   = (float4*)(sVs + DV);  // CS*DV4 float4s (offset 87360 B, 16B aligned)

    const int bh = blockIdx.x, ch = blockIdx.y, tid = threadIdx.x;
    const float*  kb = k + ((size_t)bh * SEQ + (size_t)ch * CS) * D;
    const float4* vb = (const float4*)(v + ((size_t)bh * SEQ + (size_t)ch * CS) * DV);
    const float*  st = g_state + (size_t)(bh * NCH + ch) * ST_SIZE;

    for (int i = tid; i < CS * D;   i += 256) sk[i]    = kb[i];
    for (int i = tid; i < CS * DV4; i += 256) sv[i]    = vb[i];
    for (int i = tid; i < 16384;    i += 256) sKKV[i]  = st[i];
    for (int i = tid; i < 1360;     i += 256) sTail[i] = st[16384 + i];
    __syncthreads();

    const int w    = tid >> 5, lane = tid & 31;
    const int tb   = (w < 4) ? w : 11 - w;      // SMSP load balancing
    const int t    = tb * 32 + lane;

    float qr[D];
    const float4* qb = (const float4*)(q + ((size_t)bh * SEQ + (size_t)ch * CS + t) * D);
#pragma unroll
    for (int i = 0; i < 4; i++) {
        const float4 qq = qb[i];
        qr[4*i+0] = qq.x * 0.25f;  qr[4*i+1] = qq.y * 0.25f;
        qr[4*i+2] = qq.z * 0.25f;  qr[4*i+3] = qq.w * 0.25f;
    }

    float4 acc[DV4];
    const float4* vs4 = (const float4*)sVs;
#pragma unroll
    for (int j = 0; j < DV4; j++) acc[j] = vs4[j];     // "1"-term: sum of prev v
    float z = (float)(ch * CS);                        // "1"-term: prev token count

    // ---- inter linear: o += q . KV_prev ; z += q . Ksum_prev ----
    const float4* kv4 = (const float4*)sKV;
    for (int dd = 0; dd < D; dd++) {
        const float wq = qr[dd];
        z = fmaf(wq, sKs[dd], z);
#pragma unroll
        for (int j = 0; j < DV4; j++) {
            const float4 m = kv4[dd * DV4 + j];
            acc[j].x = fmaf(wq, m.x, acc[j].x);
            acc[j].y = fmaf(wq, m.y, acc[j].y);
            acc[j].z = fmaf(wq, m.z, acc[j].z);
            acc[j].w = fmaf(wq, m.w, acc[j].w);
        }
    }

    // ---- inter quadratic (symmetric: d<=e, diag halved) ----
    for (int dd = 0; dd < D; dd++) {
        for (int ee = dd; ee < D; ee++) {
            float wq = qr[dd] * qr[ee];
            if (ee == dd) wq *= 0.5f;
            z = fmaf(wq, sKK[dd * 16 + ee], z);
            const float4* m4 = (const float4*)(sKKV + (dd * 16 + ee) * DV);
#pragma unroll
            for (int j = 0; j < DV4; j++) {
                const float4 m = m4[j];
                acc[j].x = fmaf(wq, m.x, acc[j].x);
                acc[j].y = fmaf(wq, m.y, acc[j].y);
                acc[j].z = fmaf(wq, m.z, acc[j].z);
                acc[j].w = fmaf(wq, m.w, acc[j].w);
            }
        }
    }

    // ---- intra-chunk causal: warp-uniform bound, predicated weight ----
    const int smax = tb * 32 + 31;
    for (int s = 0; s <= smax; s++) {
        const float* kr = sk + s * D;
        float S = 0.f;
#pragma unroll
        for (int i = 0; i < D; i++) S = fmaf(qr[i], kr[i], S);
        float wgt = 1.0f + S + 0.5f * S * S;
        wgt = (s <= t) ? wgt : 0.0f;
        z += wgt;
        const float4* vr = sv + s * DV4;
#pragma unroll
        for (int j = 0; j < DV4; j++) {
            const float4 vv = vr[j];
            acc[j].x = fmaf(wgt, vv.x, acc[j].x);
            acc[j].y = fmaf(wgt, vv.y, acc[j].y);
            acc[j].z = fmaf(wgt, vv.z, acc[j].z);
            acc[j].w = fmaf(wgt, vv.w, acc[j].w);
        }
    }

    const float inv = 1.0f / (z + 1e-6f);
    float4* ob = (float4*)(out + ((size_t)bh * SEQ + (size_t)ch * CS + t) * DV);
#pragma unroll
    for (int j = 0; j < DV4; j++)
        ob[j] = make_float4(acc[j].x * inv, acc[j].y * inv,
                            acc[j].z * inv, acc[j].w * inv);
}

// ---------------------------------------------------------------------------
extern "C" void kernel_launch(void* const* d_in, const int* in_sizes, int n_in,
                              void* d_out, int out_size)
{
    const float* q = (const float*)d_in[0];
    const float* k = (const float*)d_in[1];
    const float* v = (const float*)d_in[2];
    float* out = (float*)d_out;

    const int smem1 = (CS * D + CS * DV) * 4;                       // 81920 B
    const int smem3 = (CS * D + 16384 + 1360 + CS * DV) * 4;        // 152896 B
    cudaFuncSetAttribute(k1_chunk_sums, cudaFuncAttributeMaxDynamicSharedMemorySize, smem1);
    cudaFuncSetAttribute(k3_output,     cudaFuncAttributeMaxDynamicSharedMemorySize, smem3);

    dim3 grid(BH, NCH);
    k1_chunk_sums<<<grid, 256, smem1>>>(k, v);
    k2_prefix<<<dim3(BH, 18), 256>>>();
    k3_output<<<grid, 256, smem3>>>(q, k, v, out);
}

// round 2
// speedup vs baseline: 1.9250x; 1.9250x over previous
#include <cuda_runtime.h>
#include <cuda_bf16.h>
#include <cstdint>

#define BH   32
#define NCH  16
#define CS   256
#define D    16
#define DV   64
#define SEQ  4096

// state per (bh,chunk): KKVext[256][72], KVext[16][72], Vsum[72]
#define ST2_KV   18432
#define ST2_V    19584
#define ST2_SIZE 19656

__device__ float g_state[(size_t)BH * NCH * ST2_SIZE];   // ~40 MB scratch

// ---------------------------------------------------------------------------
__device__ __forceinline__ uint32_t pack_bf(float a, float b) {
    __nv_bfloat162 t = __floats2bfloat162_rn(a, b);
    return *reinterpret_cast<uint32_t*>(&t);
}
__device__ __forceinline__ void split_pack(float a, float b, uint32_t& hi, uint32_t& lo) {
    float ah = __bfloat162float(__float2bfloat16(a));
    float bh = __bfloat162float(__float2bfloat16(b));
    hi = pack_bf(ah, bh);
    lo = pack_bf(a - ah, b - bh);
}
__device__ __forceinline__ void unpack_bf(uint32_t w, float& a, float& b) {
    __nv_bfloat162 t = *reinterpret_cast<__nv_bfloat162*>(&w);
    a = __low2float(t); b = __high2float(t);
}
__device__ __forceinline__ void mma16816(float c[4], const uint32_t a[4],
                                         uint32_t b0, uint32_t b1) {
    asm volatile(
        "mma.sync.aligned.m16n8k16.row.col.f32.bf16.bf16.f32 "
        "{%0,%1,%2,%3}, {%4,%5,%6,%7}, {%8,%9}, {%0,%1,%2,%3};\n"
        : "+f"(c[0]), "+f"(c[1]), "+f"(c[2]), "+f"(c[3])
        : "r"(a[0]), "r"(a[1]), "r"(a[2]), "r"(a[3]), "r"(b0), "r"(b1));
}

// ---------------------------------------------------------------------------
// K1: per-chunk sums via MMA.  C[256de,72] = W[de,c] @ Vext[c,72]
// Vext col64 = 1 -> col64 of C = KK.  KVext/Vsum via SIMT (tiny).
// ---------------------------------------------------------------------------
__global__ __launch_bounds__(256) void k1_sums(
    const float* __restrict__ k, const float* __restrict__ v)
{
    extern __shared__ char smem[];
    float*    sK  = (float*)smem;                       // 256*17 floats
    uint32_t* sVh = (uint32_t*)(smem + 17408);          // 128*72
    uint32_t* sVl = (uint32_t*)(smem + 17408 + 36864);  // 128*72

    const int bh = blockIdx.x, ch = blockIdx.y;
    const int tid = threadIdx.x, lane = tid & 31, wid = tid >> 5;
    const int qr = lane >> 2, qc = lane & 3;
    const float* kb = k + ((size_t)bh * SEQ + (size_t)ch * CS) * D;
    const float* vb = v + ((size_t)bh * SEQ + (size_t)ch * CS) * DV;

    for (int i = tid; i < CS * D; i += 256) sK[(i >> 4) * 17 + (i & 15)] = kb[i];
    for (int w = tid; w < 128 * 72; w += 256) {
        int cp = w / 72, f = w - cp * 72;
        float v0, v1;
        if (f < 64)      { v0 = vb[cp * 128 + f]; v1 = vb[cp * 128 + 64 + f]; }
        else if (f == 64){ v0 = 1.f; v1 = 1.f; }
        else             { v0 = 0.f; v1 = 0.f; }
        split_pack(v0, v1, sVh[w], sVl[w]);
    }
    __syncthreads();

    float acc[2][9][4];
#pragma unroll
    for (int ms = 0; ms < 2; ms++)
#pragma unroll
        for (int nt = 0; nt < 9; nt++)
#pragma unroll
            for (int j = 0; j < 4; j++) acc[ms][nt][j] = 0.f;

    for (int ks = 0; ks < 16; ks++) {
        uint32_t Ah[2][4], Al[2][4];
        const int c0 = ks * 16 + 2 * qc;
#pragma unroll
        for (int ms = 0; ms < 2; ms++) {
            const int row = wid * 32 + ms * 16 + qr;
            const int d = row >> 4, e0 = row & 15, e1 = e0 + 8;
            float p[8];
#pragma unroll
            for (int j = 0; j < 4; j++) {
                const int cc = c0 + ((j & 2) ? 8 : 0) + (j & 1);
                // cc order: c0, c0+1, c0+8, c0+9
                const float kdv = sK[cc * 17 + d];
                p[j]     = kdv * sK[cc * 17 + e0];
                p[4 + j] = kdv * sK[cc * 17 + e1];
            }
            split_pack(p[0], p[1], Ah[ms][0], Al[ms][0]);   // row_lo  c0,c0+1
            split_pack(p[4], p[5], Ah[ms][1], Al[ms][1]);   // row_hi  c0,c0+1
            split_pack(p[2], p[3], Ah[ms][2], Al[ms][2]);   // row_lo  c0+8,+9
            split_pack(p[6], p[7], Ah[ms][3], Al[ms][3]);   // row_hi  c0+8,+9
        }
        const int b0i = (ks * 8 + qc) * 72 + qr;
        const int b1i = b0i + 4 * 72;
#pragma unroll
        for (int nt = 0; nt < 9; nt++) {
            const uint32_t bh0 = sVh[b0i + nt * 8], bh1 = sVh[b1i + nt * 8];
            const uint32_t bl0 = sVl[b0i + nt * 8], bl1 = sVl[b1i + nt * 8];
#pragma unroll
            for (int ms = 0; ms < 2; ms++) {
                mma16816(acc[ms][nt], Ah[ms], bh0, bh1);
                mma16816(acc[ms][nt], Ah[ms], bl0, bl1);
                mma16816(acc[ms][nt], Al[ms], bh0, bh1);
            }
        }
    }

    float* st = g_state + (size_t)(bh * NCH + ch) * ST2_SIZE;
#pragma unroll
    for (int ms = 0; ms < 2; ms++) {
        const int row = wid * 32 + ms * 16 + qr;
#pragma unroll
        for (int nt = 0; nt < 9; nt++) {
            const int col = nt * 8 + 2 * qc;
            *(float2*)(st + row * 72 + col)       = make_float2(acc[ms][nt][0], acc[ms][nt][1]);
            *(float2*)(st + (row + 8) * 72 + col) = make_float2(acc[ms][nt][2], acc[ms][nt][3]);
        }
    }

    // KVext (16x72, col64 = Ksum) + Vsum (72) via SIMT
    for (int idx = tid; idx < 16 * 72; idx += 256) {
        const int d = idx / 72, f = idx - d * 72;
        float a = 0.f;
        if (f <= 64) {
            for (int cp = 0; cp < 128; cp++) {
                float v0h, v1h, v0l, v1l;
                unpack_bf(sVh[cp * 72 + f], v0h, v1h);
                unpack_bf(sVl[cp * 72 + f], v0l, v1l);
                a = fmaf(sK[(2 * cp) * 17 + d],     v0h + v0l, a);
                a = fmaf(sK[(2 * cp + 1) * 17 + d], v1h + v1l, a);
            }
        }
        st[ST2_KV + idx] = a;
    }
    if (tid < 72) {
        float a = 0.f;
        if (tid < 64) {
            for (int cp = 0; cp < 128; cp++) {
                float v0h, v1h, v0l, v1l;
                unpack_bf(sVh[cp * 72 + tid], v0h, v1h);
                unpack_bf(sVl[cp * 72 + tid], v0l, v1l);
                a += (v0h + v0l) + (v1h + v1l);
            }
        }
        st[ST2_V + tid] = a;
    }
}

// ---------------------------------------------------------------------------
// K2: exclusive prefix over chunk axis
// ---------------------------------------------------------------------------
__global__ __launch_bounds__(256) void k2_prefix()
{
    const int bh = blockIdx.x;
    int idx = blockIdx.y * 256 + threadIdx.x;
    const int stride = gridDim.y * 256;
    float* base = g_state + (size_t)bh * NCH * ST2_SIZE;
    for (; idx < ST2_SIZE; idx += stride) {
        float run = 0.f;
#pragma unroll
        for (int c = 0; c < NCH; c++) {
            float* p = base + (size_t)c * ST2_SIZE + idx;
            const float t = *p; *p = run; run += t;
        }
    }
}

// ---------------------------------------------------------------------------
// K3: O[256,72] = Wq @ KKVext + [qhat|const] @ [KVext;constrow] + A_intra @ Vext
// col 64 of O accumulates z.  out = O[:, :64] / (z + 1e-6)
// ---------------------------------------------------------------------------
__global__ __launch_bounds__(256) void k3_output(
    const float* __restrict__ q, const float* __restrict__ k,
    const float* __restrict__ v, float* __restrict__ out)
{
    extern __shared__ char smem[];
    uint32_t* sSth = (uint32_t*)smem;        // 9216  KKVext hi (pair-major)
    uint32_t* sStl = sSth + 9216;            // 9216  KKVext lo
    uint32_t* sVh  = sStl + 9216;            // 9216  Vext hi
    uint32_t* sVl  = sVh  + 9216;            // 9216  Vext lo
    uint32_t* sKph = sVl  + 9216;            // 2048  k pair-major [d/2][s]
    uint32_t* sKpl = sKph + 2048;
    uint32_t* sQh  = sKpl + 2048;            // 2048  qhat pair-major [t][d/2]
    uint32_t* sQl  = sQh  + 2048;
    uint32_t* sLh  = sQl  + 2048;            // 648   [KVext;constrow] pairs
    uint32_t* sLl  = sLh  + 648;
    float*    sQ   = (float*)(sLl + 648);    // 256*17 fp32 qhat

    const int bh = blockIdx.x, ch = blockIdx.y;
    const int tid = threadIdx.x, lane = tid & 31, wid = tid >> 5;
    const int qr = lane >> 2, qc = lane & 3;
    const float* qb = q + ((size_t)bh * SEQ + (size_t)ch * CS) * D;
    const float* kb = k + ((size_t)bh * SEQ + (size_t)ch * CS) * D;
    const float* vb = v + ((size_t)bh * SEQ + (size_t)ch * CS) * DV;
    const float* st = g_state + (size_t)(bh * NCH + ch) * ST2_SIZE;

    for (int w = tid; w < 2048; w += 256) {
        {   // qhat pairs + fp32 copy
            float2 qv = ((const float2*)qb)[w];
            const float x = qv.x * 0.25f, y = qv.y * 0.25f;
            split_pack(x, y, sQh[w], sQl[w]);
            const int t = w >> 3, dp = w & 7;
            sQ[t * 17 + 2 * dp] = x;  sQ[t * 17 + 2 * dp + 1] = y;
        }
        {   // k pairs along d:  word[(d/2)*256 + s]
            const int s = w & 255, dpp = w >> 8;
            float2 kv2 = ((const float2*)kb)[s * 8 + dpp];
            split_pack(kv2.x, kv2.y, sKph[w], sKpl[w]);
        }
    }
    for (int w = tid; w < 9216; w += 256) {
        const int dep = w / 72, f = w - dep * 72;
        split_pack(st[(2 * dep) * 72 + f], st[(2 * dep + 1) * 72 + f], sSth[w], sStl[w]);
        float v0, v1;
        if (f < 64)      { v0 = vb[dep * 128 + f]; v1 = vb[dep * 128 + 64 + f]; }
        else if (f == 64){ v0 = 1.f; v1 = 1.f; }
        else             { v0 = 0.f; v1 = 0.f; }
        split_pack(v0, v1, sVh[w], sVl[w]);
    }
    for (int w = tid; w < 648; w += 256) {
        const int kp = w / 72, f = w - kp * 72;
        float a, b;
        if (kp < 8) {
            a = st[ST2_KV + (2 * kp) * 72 + f];
            b = st[ST2_KV + (2 * kp + 1) * 72 + f];
        } else {   // rows 16 (const) ,17 (zero)
            a = (f < 64) ? st[ST2_V + f] : (f == 64 ? (float)(ch * CS) : 0.f);
            b = 0.f;
        }
        split_pack(a, b, sLh[w], sLl[w]);
    }
    __syncthreads();

    float O[2][9][4];
#pragma unroll
    for (int ms = 0; ms < 2; ms++)
#pragma unroll
        for (int nt = 0; nt < 9; nt++)
#pragma unroll
            for (int j = 0; j < 4; j++) O[ms][nt][j] = 0.f;

    // interleaved row mapping: ms -> rows ms*128 + wid*16 + qr (+8)
    const int rbase[2] = { wid * 16 + qr, 128 + wid * 16 + qr };

    // ---- part 1: Wq[t,de]=0.5*qd*qe  @  KKVext ----
    for (int ks = 0; ks < 16; ks++) {
        uint32_t Ah[2][4], Al[2][4];
        const int d = ks, e0 = 2 * qc;
#pragma unroll
        for (int ms = 0; ms < 2; ms++) {
            const int rlo = rbase[ms], rhi = rlo + 8;
            const float* qlo = sQ + rlo * 17;
            const float* qhi = sQ + rhi * 17;
            const float qd0 = 0.5f * qlo[d];
            const float qd1 = 0.5f * qhi[d];
            split_pack(qd0 * qlo[e0],     qd0 * qlo[e0 + 1], Ah[ms][0], Al[ms][0]);
            split_pack(qd1 * qhi[e0],     qd1 * qhi[e0 + 1], Ah[ms][1], Al[ms][1]);
            split_pack(qd0 * qlo[e0 + 8], qd0 * qlo[e0 + 9], Ah[ms][2], Al[ms][2]);
            split_pack(qd1 * qhi[e0 + 8], qd1 * qhi[e0 + 9], Ah[ms][3], Al[ms][3]);
        }
        const int b0i = (ks * 8 + qc) * 72 + qr, b1i = b0i + 288;
#pragma unroll
        for (int nt = 0; nt < 9; nt++) {
            const uint32_t bh0 = sSth[b0i + nt * 8], bh1 = sSth[b1i + nt * 8];
            const uint32_t bl0 = sStl[b0i + nt * 8], bl1 = sStl[b1i + nt * 8];
#pragma unroll
            for (int ms = 0; ms < 2; ms++) {
                mma16816(O[ms][nt], Ah[ms], bh0, bh1);
                mma16816(O[ms][nt], Ah[ms], bl0, bl1);
                mma16816(O[ms][nt], Al[ms], bh0, bh1);
            }
        }
    }

    // q A-fragments (used by linear part and S MMAs)
    uint32_t Aq_h[2][4], Aq_l[2][4];
#pragma unroll
    for (int ms = 0; ms < 2; ms++) {
        const int rlo = rbase[ms], rhi = rlo + 8;
        Aq_h[ms][0] = sQh[rlo * 8 + qc];     Aq_l[ms][0] = sQl[rlo * 8 + qc];
        Aq_h[ms][1] = sQh[rhi * 8 + qc];     Aq_l[ms][1] = sQl[rhi * 8 + qc];
        Aq_h[ms][2] = sQh[rlo * 8 + qc + 4]; Aq_l[ms][2] = sQl[rlo * 8 + qc + 4];
        Aq_h[ms][3] = sQh[rhi * 8 + qc + 4]; Aq_l[ms][3] = sQl[rhi * 8 + qc + 4];
    }

    // ---- part 2: linear (qhat @ KVext) + const row (Vsum_prev, count) ----
    {
        const int b0i = qc * 72 + qr, b1i = b0i + 288;
        const uint32_t onesA = (qc == 0) ? 0x00003F80u : 0u;   // bf16 1.0 in low half
        const uint32_t Ac[4] = { onesA, onesA, 0u, 0u };
#pragma unroll
        for (int nt = 0; nt < 9; nt++) {
            const uint32_t bh0 = sLh[b0i + nt * 8], bh1 = sLh[b1i + nt * 8];
            const uint32_t bl0 = sLl[b0i + nt * 8], bl1 = sLl[b1i + nt * 8];
            const uint32_t cb_h = (qc == 0) ? sLh[576 + nt * 8 + qr] : 0u;
            const uint32_t cb_l = (qc == 0) ? sLl[576 + nt * 8 + qr] : 0u;
#pragma unroll
            for (int ms = 0; ms < 2; ms++) {
                mma16816(O[ms][nt], Aq_h[ms], bh0, bh1);
                mma16816(O[ms][nt], Aq_h[ms], bl0, bl1);
                mma16816(O[ms][nt], Aq_l[ms], bh0, bh1);
                mma16816(O[ms][nt], Ac, cb_h, 0u);
                mma16816(O[ms][nt], Ac, cb_l, 0u);
            }
        }
    }

    // ---- part 3: intra-chunk causal A = tril(1+S+0.5S^2), fused S->A->O ----
#pragma unroll
    for (int ms = 0; ms < 2; ms++) {
        const int sulim = ms * 8 + wid;     // last s-16-unit touching this row tile
        for (int su = 0; su <= sulim; su++) {
            const int sbase = su * 16;
            float s0[4] = {0.f, 0.f, 0.f, 0.f};
            float s1[4] = {0.f, 0.f, 0.f, 0.f};
            const int bk0 = qc * 256 + sbase + qr;
            const int bk1 = bk0 + 1024;
            mma16816(s0, Aq_h[ms], sKph[bk0], sKph[bk1]);
            mma16816(s0, Aq_h[ms], sKpl[bk0], sKpl[bk1]);
            mma16816(s0, Aq_l[ms], sKph[bk0], sKph[bk1]);
            mma16816(s1, Aq_h[ms], sKph[bk0 + 8], sKph[bk1 + 8]);
            mma16816(s1, Aq_h[ms], sKpl[bk0 + 8], sKpl[bk1 + 8]);
            mma16816(s1, Aq_l[ms], sKph[bk0 + 8], sKph[bk1 + 8]);

            const int rlo = rbase[ms], rhi = rlo + 8;
            const int c0 = sbase + 2 * qc;
            float a00 = (c0     <= rlo) ? fmaf(0.5f * s0[0], s0[0], 1.f + s0[0]) : 0.f;
            float a01 = (c0 + 1 <= rlo) ? fmaf(0.5f * s0[1], s0[1], 1.f + s0[1]) : 0.f;
            float a10 = (c0     <= rhi) ? fmaf(0.5f * s0[2], s0[2], 1.f + s0[2]) : 0.f;
            float a11 = (c0 + 1 <= rhi) ? fmaf(0.5f * s0[3], s0[3], 1.f + s0[3]) : 0.f;
            float a20 = (c0 + 8 <= rlo) ? fmaf(0.5f * s1[0], s1[0], 1.f + s1[0]) : 0.f;
            float a21 = (c0 + 9 <= rlo) ? fmaf(0.5f * s1[1], s1[1], 1.f + s1[1]) : 0.f;
            float a30 = (c0 + 8 <= rhi) ? fmaf(0.5f * s1[2], s1[2], 1.f + s1[2]) : 0.f;
            float a31 = (c0 + 9 <= rhi) ? fmaf(0.5f * s1[3], s1[3], 1.f + s1[3]) : 0.f;

            uint32_t AH[4], AL[4];
            split_pack(a00, a01, AH[0], AL[0]);
            split_pack(a10, a11, AH[1], AL[1]);
            split_pack(a20, a21, AH[2], AL[2]);
            split_pack(a30, a31, AH[3], AL[3]);

            const int vb0 = ((sbase >> 1) + qc) * 72 + qr;
            const int vb1 = vb0 + 288;
#pragma unroll
            for (int nt = 0; nt < 9; nt++) {
                const uint32_t bh0 = sVh[vb0 + nt * 8], bh1 = sVh[vb1 + nt * 8];
                const uint32_t bl0 = sVl[vb0 + nt * 8], bl1 = sVl[vb1 + nt * 8];
                mma16816(O[ms][nt], AH, bh0, bh1);
                mma16816(O[ms][nt], AH, bl0, bl1);
                mma16816(O[ms][nt], AL, bh0, bh1);
            }
        }
    }

    // ---- epilogue: z = col 64, divide, store ----
#pragma unroll
    for (int ms = 0; ms < 2; ms++) {
        const float zlo = __shfl_sync(0xffffffffu, O[ms][8][0], lane & 28);
        const float zhi = __shfl_sync(0xffffffffu, O[ms][8][2], lane & 28);
        const float ilo = 1.f / (zlo + 1e-6f);
        const float ihi = 1.f / (zhi + 1e-6f);
        const int rlo = rbase[ms];
        float* olo = out + ((size_t)bh * SEQ + (size_t)ch * CS + rlo) * DV;
        float* ohi = olo + 8 * DV;
#pragma unroll
        for (int nt = 0; nt < 8; nt++) {
            const int col = nt * 8 + 2 * qc;
            *(float2*)(olo + col) = make_float2(O[ms][nt][0] * ilo, O[ms][nt][1] * ilo);
            *(float2*)(ohi + col) = make_float2(O[ms][nt][2] * ihi, O[ms][nt][3] * ihi);
        }
    }
}

// ---------------------------------------------------------------------------
extern "C" void kernel_launch(void* const* d_in, const int* in_sizes, int n_in,
                              void* d_out, int out_size)
{
    const float* q = (const float*)d_in[0];
    const float* k = (const float*)d_in[1];
    const float* v = (const float*)d_in[2];
    float* out = (float*)d_out;

    const int smem1 = 17408 + 2 * 36864;                     // 91136 B
    const int smem3 = (4 * 9216 + 4 * 2048 + 2 * 648) * 4 + 17408;  // 202816 B
    cudaFuncSetAttribute(k1_sums,   cudaFuncAttributeMaxDynamicSharedMemorySize, smem1);
    cudaFuncSetAttribute(k3_output, cudaFuncAttributeMaxDynamicSharedMemorySize, smem3);

    dim3 grid(BH, NCH);
    k1_sums<<<grid, 256, smem1>>>(k, v);
    k2_prefix<<<dim3(BH, 20), 256>>>();
    k3_output<<<grid, 256, smem3>>>(q, k, v, out);
}

// round 6
// speedup vs baseline: 2.6532x; 1.3783x over previous
#include <cuda_runtime.h>
#include <cuda_bf16.h>
#include <cstdint>

#define BH   32
#define NCH  16
#define CS   256
#define D    16
#define DV   64
#define SEQ  4096
#define NPP  144     // 136 (d<=e) pairs padded to 144

// state per (bh,chunk): KKVsym[144][72], KVext[16][72], Vsum[72]
#define ST_KV   10368
#define ST_V    11520
#define ST_SIZE 11592

__device__ float g_state[(size_t)BH * NCH * ST_SIZE];   // ~23.7 MB scratch

// ---- pair table (d<=e), constexpr-initialized constant memory -------------
struct PairTab { unsigned char d[NPP]; unsigned char e[NPP]; float cw[NPP]; };
__host__ __device__ constexpr PairTab mk_tab() {
    PairTab t{};
    int p = 0;
    for (int d = 0; d < 16; d++)
        for (int e = d; e < 16; e++) {
            t.d[p] = (unsigned char)d; t.e[p] = (unsigned char)e;
            t.cw[p] = (d == e) ? 0.5f : 1.0f; p++;
        }
    for (; p < NPP; p++) { t.d[p] = 0; t.e[p] = 0; t.cw[p] = 0.f; }
    return t;
}
__constant__ PairTab cPT = mk_tab();

// ---------------------------------------------------------------------------
__device__ __forceinline__ void split_pack(float a, float b, uint32_t& hi, uint32_t& lo) {
    uint32_t h;
    asm("cvt.rn.bf16x2.f32 %0, %1, %2;" : "=r"(h) : "f"(b), "f"(a));
    const float ah = __uint_as_float(h << 16);
    const float bh = __uint_as_float(h & 0xffff0000u);
    uint32_t l;
    asm("cvt.rn.bf16x2.f32 %0, %1, %2;" : "=r"(l) : "f"(b - bh), "f"(a - ah));
    hi = h; lo = l;
}
__device__ __forceinline__ void unpack_bf(uint32_t w, float& a, float& b) {
    a = __uint_as_float(w << 16);
    b = __uint_as_float(w & 0xffff0000u);
}
__device__ __forceinline__ void mma16816(float c[4], const uint32_t a[4],
                                         uint32_t b0, uint32_t b1) {
    asm volatile(
        "mma.sync.aligned.m16n8k16.row.col.f32.bf16.bf16.f32 "
        "{%0,%1,%2,%3}, {%4,%5,%6,%7}, {%8,%9}, {%0,%1,%2,%3};\n"
        : "+f"(c[0]), "+f"(c[1]), "+f"(c[2]), "+f"(c[3])
        : "r"(a[0]), "r"(a[1]), "r"(a[2]), "r"(a[3]), "r"(b0), "r"(b1));
}

// ---------------------------------------------------------------------------
// K1: KKVsym[144,72] = W[pair,c] @ Vext[c,72]  (Vext col64 = 1)
//     KVext[16,72]   = K^T @ Vext   (MMA, n-tiles across warps)
//     Vsum[72]       = column sums (SIMT + shfl)
// 288 threads = 9 warps; warp w owns m-tile w of the 144-row GEMM.
// ---------------------------------------------------------------------------
__global__ __launch_bounds__(288, 2) void k1_sums(
    const float* __restrict__ k, const float* __restrict__ v)
{
    extern __shared__ char smem[];
    float*    sK  = (float*)smem;                       // 256*17 floats
    uint32_t* sVh = (uint32_t*)(smem + 17408);          // 128*72
    uint32_t* sVl = sVh + 9216;                         // 128*72

    const int bh = blockIdx.x, ch = blockIdx.y;
    const int tid = threadIdx.x, lane = tid & 31, w = tid >> 5;
    const int qr = lane >> 2, qc = lane & 3;
    const float* kb = k + ((size_t)bh * SEQ + (size_t)ch * CS) * D;
    const float* vb = v + ((size_t)bh * SEQ + (size_t)ch * CS) * DV;

    for (int i = tid; i < CS * D; i += 288) sK[(i >> 4) * 17 + (i & 15)] = kb[i];
    for (int i = tid; i < 128 * 72; i += 288) {
        const int cp = i / 72, f = i - cp * 72;
        float v0, v1;
        if (f < 64)       { v0 = vb[cp * 128 + f]; v1 = vb[cp * 128 + 64 + f]; }
        else if (f == 64) { v0 = 1.f; v1 = 1.f; }
        else              { v0 = 0.f; v1 = 0.f; }
        split_pack(v0, v1, sVh[i], sVl[i]);
    }
    __syncthreads();

    const int p0 = w * 16 + qr, p1 = p0 + 8;
    const int d0 = cPT.d[p0], e0 = cPT.e[p0];
    const int d1 = cPT.d[p1], e1 = cPT.e[p1];

    float acc[9][4];
#pragma unroll
    for (int nt = 0; nt < 9; nt++)
#pragma unroll
        for (int j = 0; j < 4; j++) acc[nt][j] = 0.f;

    for (int ks = 0; ks < 16; ks++) {
        const int cA = ks * 16 + 2 * qc, cB = cA + 1, cC = cA + 8, cD = cA + 9;
        const float* rA = sK + cA * 17; const float* rB = sK + cB * 17;
        const float* rC = sK + cC * 17; const float* rD = sK + cD * 17;
        uint32_t Ah[4], Al[4];
        split_pack(rA[d0] * rA[e0], rB[d0] * rB[e0], Ah[0], Al[0]);
        split_pack(rA[d1] * rA[e1], rB[d1] * rB[e1], Ah[1], Al[1]);
        split_pack(rC[d0] * rC[e0], rD[d0] * rD[e0], Ah[2], Al[2]);
        split_pack(rC[d1] * rC[e1], rD[d1] * rD[e1], Ah[3], Al[3]);

        const int b0i = (ks * 8 + qc) * 72 + qr, b1i = b0i + 288;
#pragma unroll
        for (int nt = 0; nt < 9; nt++) {
            const uint32_t bh0 = sVh[b0i + nt * 8], bh1 = sVh[b1i + nt * 8];
            const uint32_t bl0 = sVl[b0i + nt * 8], bl1 = sVl[b1i + nt * 8];
            mma16816(acc[nt], Ah, bh0, bh1);
            mma16816(acc[nt], Ah, bl0, bl1);
            mma16816(acc[nt], Al, bh0, bh1);
        }
    }

    float* st = g_state + (size_t)(bh * NCH + ch) * ST_SIZE;
#pragma unroll
    for (int nt = 0; nt < 9; nt++) {
        const int col = nt * 8 + 2 * qc;
        *(float2*)(st + p0 * 72 + col) = make_float2(acc[nt][0], acc[nt][1]);
        *(float2*)(st + p1 * 72 + col) = make_float2(acc[nt][2], acc[nt][3]);
    }

    // ---- KVext[16,72] = K^T @ Vext : warp w computes n-tile w ----
    {
        float kv[4] = {0.f, 0.f, 0.f, 0.f};
        for (int ks = 0; ks < 16; ks++) {
            const int cA = ks * 16 + 2 * qc, cB = cA + 1, cC = cA + 8, cD = cA + 9;
            uint32_t Ah[4], Al[4];
            split_pack(sK[cA * 17 + qr],     sK[cB * 17 + qr],     Ah[0], Al[0]);
            split_pack(sK[cA * 17 + qr + 8], sK[cB * 17 + qr + 8], Ah[1], Al[1]);
            split_pack(sK[cC * 17 + qr],     sK[cD * 17 + qr],     Ah[2], Al[2]);
            split_pack(sK[cC * 17 + qr + 8], sK[cD * 17 + qr + 8], Ah[3], Al[3]);
            const int b0i = (ks * 8 + qc) * 72 + w * 8 + qr, b1i = b0i + 288;
            const uint32_t bh0 = sVh[b0i], bh1 = sVh[b1i];
            const uint32_t bl0 = sVl[b0i], bl1 = sVl[b1i];
            mma16816(kv, Ah, bh0, bh1);
            mma16816(kv, Ah, bl0, bl1);
            mma16816(kv, Al, bh0, bh1);
        }
        const int col = w * 8 + 2 * qc;
        *(float2*)(st + ST_KV + qr * 72 + col)       = make_float2(kv[0], kv[1]);
        *(float2*)(st + ST_KV + (qr + 8) * 72 + col) = make_float2(kv[2], kv[3]);
    }

    // ---- Vsum[72] : 4 threads per column + shfl reduce ----
    {
        const int f = tid >> 2, qt = tid & 3;
        float s = 0.f;
#pragma unroll 4
        for (int r = qt * 32; r < qt * 32 + 32; r++) {
            float a, b, c, d2;
            unpack_bf(sVh[r * 72 + f], a, b);
            unpack_bf(sVl[r * 72 + f], c, d2);
            s += (a + c) + (b + d2);
        }
        s += __shfl_xor_sync(0xffffffffu, s, 1);
        s += __shfl_xor_sync(0xffffffffu, s, 2);
        if (qt == 0) st[ST_V + f] = s;
    }
}

// ---------------------------------------------------------------------------
// K2: exclusive prefix over chunk axis
// ---------------------------------------------------------------------------
__global__ __launch_bounds__(256) void k2_prefix()
{
    const int bh = blockIdx.x;
    int idx = blockIdx.y * 256 + threadIdx.x;
    const int stride = gridDim.y * 256;
    float* base = g_state + (size_t)bh * NCH * ST_SIZE;
    for (; idx < ST_SIZE; idx += stride) {
        float run = 0.f;
#pragma unroll
        for (int c = 0; c < NCH; c++) {
            float* p = base + (size_t)c * ST_SIZE + idx;
            const float t = *p; *p = run; run += t;
        }
    }
}

// ---------------------------------------------------------------------------
// K3: O[256,72] = Wq_sym @ KKVsym + [qhat|1] @ [KVext;Vsumrow] + A_intra @ Vext
// col 64 of O accumulates z (Vsum[64] = prefixed token count).
// ---------------------------------------------------------------------------
__global__ __launch_bounds__(256) void k3_output(
    const float* __restrict__ q, const float* __restrict__ k,
    const float* __restrict__ v, float* __restrict__ out)
{
    extern __shared__ char smem[];
    uint32_t* sSth = (uint32_t*)smem;        // 5184  KKVsym hi (pair-pair major)
    uint32_t* sStl = sSth + 5184;            // 5184
    uint32_t* sVh  = sStl + 5184;            // 9216  Vext hi
    uint32_t* sVl  = sVh  + 9216;            // 9216
    uint32_t* sKph = sVl  + 9216;            // 2048  k pair-major [d/2][s]
    uint32_t* sKpl = sKph + 2048;
    uint32_t* sQh  = sKpl + 2048;            // 2048  qhat pair-major [t][d/2]
    uint32_t* sQl  = sQh  + 2048;
    uint32_t* sLh  = sQl  + 2048;            // 648   [KVext;Vsumrow;0]
    uint32_t* sLl  = sLh  + 648;
    float*    sQ   = (float*)(sLl + 648);    // 256*17 fp32 qhat

    const int bh = blockIdx.x, ch = blockIdx.y;
    const int tid = threadIdx.x, lane = tid & 31, wid = tid >> 5;
    const int qr = lane >> 2, qc = lane & 3;
    const float* qb = q + ((size_t)bh * SEQ + (size_t)ch * CS) * D;
    const float* kb = k + ((size_t)bh * SEQ + (size_t)ch * CS) * D;
    const float* vb = v + ((size_t)bh * SEQ + (size_t)ch * CS) * DV;
    const float* st = g_state + (size_t)(bh * NCH + ch) * ST_SIZE;

    for (int w = tid; w < 2048; w += 256) {
        {   // qhat pairs + fp32 copy
            float2 qv = ((const float2*)qb)[w];
            const float x = qv.x * 0.25f, y = qv.y * 0.25f;
            split_pack(x, y, sQh[w], sQl[w]);
            const int t = w >> 3, dp = w & 7;
            sQ[t * 17 + 2 * dp] = x;  sQ[t * 17 + 2 * dp + 1] = y;
        }
        {   // k pairs along d: word[(d/2)*256 + s]
            const int s = w & 255, dpp = w >> 8;
            float2 kv2 = ((const float2*)kb)[s * 8 + dpp];
            split_pack(kv2.x, kv2.y, sKph[w], sKpl[w]);
        }
    }
    for (int w = tid; w < 9216; w += 256) {
        const int dep = w / 72, f = w - dep * 72;
        float v0, v1;
        if (f < 64)       { v0 = vb[dep * 128 + f]; v1 = vb[dep * 128 + 64 + f]; }
        else if (f == 64) { v0 = 1.f; v1 = 1.f; }
        else              { v0 = 0.f; v1 = 0.f; }
        split_pack(v0, v1, sVh[w], sVl[w]);
        if (w < 5184)
            split_pack(st[(2 * dep) * 72 + f], st[(2 * dep + 1) * 72 + f], sSth[w], sStl[w]);
    }
    for (int w = tid; w < 648; w += 256) {
        const int kp = w / 72, f = w - kp * 72;
        float a, b;
        if (kp < 8) {
            a = st[ST_KV + (2 * kp) * 72 + f];
            b = st[ST_KV + (2 * kp + 1) * 72 + f];
        } else {   // row 16 = prefixed Vsum (col64 = token count), row 17 = 0
            a = st[ST_V + f];
            b = 0.f;
        }
        split_pack(a, b, sLh[w], sLl[w]);
    }
    __syncthreads();

    float O[2][9][4];
#pragma unroll
    for (int ms = 0; ms < 2; ms++)
#pragma unroll
        for (int nt = 0; nt < 9; nt++)
#pragma unroll
            for (int j = 0; j < 4; j++) O[ms][nt][j] = 0.f;

    const int rbase[2] = { wid * 16 + qr, 128 + wid * 16 + qr };

    // ---- part 1: Wq_sym[t,p] = cw_p * q_d(p) * q_e(p)  @  KKVsym ----
    for (int ks = 0; ks < 9; ks++) {
        const int pA = ks * 16 + 2 * qc, pB = pA + 1, pC = pA + 8, pD = pA + 9;
        const int dA = cPT.d[pA], eA = cPT.e[pA]; const float wA = cPT.cw[pA];
        const int dB = cPT.d[pB], eB = cPT.e[pB]; const float wB = cPT.cw[pB];
        const int dC = cPT.d[pC], eC = cPT.e[pC]; const float wC = cPT.cw[pC];
        const int dD = cPT.d[pD], eD = cPT.e[pD]; const float wD = cPT.cw[pD];

        uint32_t Ah[2][4], Al[2][4];
#pragma unroll
        for (int ms = 0; ms < 2; ms++) {
            const float* qlo = sQ + rbase[ms] * 17;
            const float* qhi = qlo + 8 * 17;
            split_pack(wA * qlo[dA] * qlo[eA], wB * qlo[dB] * qlo[eB], Ah[ms][0], Al[ms][0]);
            split_pack(wA * qhi[dA] * qhi[eA], wB * qhi[dB] * qhi[eB], Ah[ms][1], Al[ms][1]);
            split_pack(wC * qlo[dC] * qlo[eC], wD * qlo[dD] * qlo[eD], Ah[ms][2], Al[ms][2]);
            split_pack(wC * qhi[dC] * qhi[eC], wD * qhi[dD] * qhi[eD], Ah[ms][3], Al[ms][3]);
        }
        const int b0i = (ks * 8 + qc) * 72 + qr, b1i = b0i + 288;
#pragma unroll
        for (int nt = 0; nt < 9; nt++) {
            const uint32_t bh0 = sSth[b0i + nt * 8], bh1 = sSth[b1i + nt * 8];
            const uint32_t bl0 = sStl[b0i + nt * 8], bl1 = sStl[b1i + nt * 8];
#pragma unroll
            for (int ms = 0; ms < 2; ms++) {
                mma16816(O[ms][nt], Ah[ms], bh0, bh1);
                mma16816(O[ms][nt], Ah[ms], bl0, bl1);
                mma16816(O[ms][nt], Al[ms], bh0, bh1);
            }
        }
    }

    // q A-fragments (linear part + S MMAs)
    uint32_t Aq_h[2][4], Aq_l[2][4];
#pragma unroll
    for (int ms = 0; ms < 2; ms++) {
        const int rlo = rbase[ms], rhi = rlo + 8;
        Aq_h[ms][0] = sQh[rlo * 8 + qc];     Aq_l[ms][0] = sQl[rlo * 8 + qc];
        Aq_h[ms][1] = sQh[rhi * 8 + qc];     Aq_l[ms][1] = sQl[rhi * 8 + qc];
        Aq_h[ms][2] = sQh[rlo * 8 + qc + 4]; Aq_l[ms][2] = sQl[rlo * 8 + qc + 4];
        Aq_h[ms][3] = sQh[rhi * 8 + qc + 4]; Aq_l[ms][3] = sQl[rhi * 8 + qc + 4];
    }

    // ---- part 2: linear (qhat @ KVext) + const row (Vsum_prev incl. count) ----
    {
        const int b0i = qc * 72 + qr, b1i = b0i + 288;
        const uint32_t onesA = (qc == 0) ? 0x00003F80u : 0u;   // bf16 1.0 low half
        const uint32_t Ac[4] = { onesA, onesA, 0u, 0u };
#pragma unroll
        for (int nt = 0; nt < 9; nt++) {
            const uint32_t bh0 = sLh[b0i + nt * 8], bh1 = sLh[b1i + nt * 8];
            const uint32_t bl0 = sLl[b0i + nt * 8], bl1 = sLl[b1i + nt * 8];
            const uint32_t cb_h = (qc == 0) ? sLh[576 + nt * 8 + qr] : 0u;
            const uint32_t cb_l = (qc == 0) ? sLl[576 + nt * 8 + qr] : 0u;
#pragma unroll
            for (int ms = 0; ms < 2; ms++) {
                mma16816(O[ms][nt], Aq_h[ms], bh0, bh1);
                mma16816(O[ms][nt], Aq_h[ms], bl0, bl1);
                mma16816(O[ms][nt], Aq_l[ms], bh0, bh1);
                mma16816(O[ms][nt], Ac, cb_h, 0u);
                mma16816(O[ms][nt], Ac, cb_l, 0u);
            }
        }
    }

    // ---- part 3: intra-chunk causal A = tril(1+S+0.5S^2), fused ----
#pragma unroll
    for (int ms = 0; ms < 2; ms++) {
        const int sulim = ms * 8 + wid;
        for (int su = 0; su <= sulim; su++) {
            const int sbase = su * 16;
            float s0[4] = {0.f, 0.f, 0.f, 0.f};
            float s1[4] = {0.f, 0.f, 0.f, 0.f};
            const int bk0 = qc * 256 + sbase + qr;
            const int bk1 = bk0 + 1024;
            mma16816(s0, Aq_h[ms], sKph[bk0], sKph[bk1]);
            mma16816(s0, Aq_h[ms], sKpl[bk0], sKpl[bk1]);
            mma16816(s0, Aq_l[ms], sKph[bk0], sKph[bk1]);
            mma16816(s1, Aq_h[ms], sKph[bk0 + 8], sKph[bk1 + 8]);
            mma16816(s1, Aq_h[ms], sKpl[bk0 + 8], sKpl[bk1 + 8]);
            mma16816(s1, Aq_l[ms], sKph[bk0 + 8], sKph[bk1 + 8]);

            const int rlo = rbase[ms], rhi = rlo + 8;
            const int c0 = sbase + 2 * qc;
            float a00 = (c0     <= rlo) ? fmaf(0.5f * s0[0], s0[0], 1.f + s0[0]) : 0.f;
            float a01 = (c0 + 1 <= rlo) ? fmaf(0.5f * s0[1], s0[1], 1.f + s0[1]) : 0.f;
            float a10 = (c0     <= rhi) ? fmaf(0.5f * s0[2], s0[2], 1.f + s0[2]) : 0.f;
            float a11 = (c0 + 1 <= rhi) ? fmaf(0.5f * s0[3], s0[3], 1.f + s0[3]) : 0.f;
            float a20 = (c0 + 8 <= rlo) ? fmaf(0.5f * s1[0], s1[0], 1.f + s1[0]) : 0.f;
            float a21 = (c0 + 9 <= rlo) ? fmaf(0.5f * s1[1], s1[1], 1.f + s1[1]) : 0.f;
            float a30 = (c0 + 8 <= rhi) ? fmaf(0.5f * s1[2], s1[2], 1.f + s1[2]) : 0.f;
            float a31 = (c0 + 9 <= rhi) ? fmaf(0.5f * s1[3], s1[3], 1.f + s1[3]) : 0.f;

            uint32_t AH[4], AL[4];
            split_pack(a00, a01, AH[0], AL[0]);
            split_pack(a10, a11, AH[1], AL[1]);
            split_pack(a20, a21, AH[2], AL[2]);
            split_pack(a30, a31, AH[3], AL[3]);

            const int vb0 = ((sbase >> 1) + qc) * 72 + qr;
            const int vb1 = vb0 + 288;
#pragma unroll
            for (int nt = 0; nt < 9; nt++) {
                const uint32_t bh0 = sVh[vb0 + nt * 8], bh1 = sVh[vb1 + nt * 8];
                const uint32_t bl0 = sVl[vb0 + nt * 8], bl1 = sVl[vb1 + nt * 8];
                mma16816(O[ms][nt], AH, bh0, bh1);
                mma16816(O[ms][nt], AH, bl0, bl1);
                mma16816(O[ms][nt], AL, bh0, bh1);
            }
        }
    }

    // ---- epilogue ----
#pragma unroll
    for (int ms = 0; ms < 2; ms++) {
        const float zlo = __shfl_sync(0xffffffffu, O[ms][8][0], lane & 28);
        const float zhi = __shfl_sync(0xffffffffu, O[ms][8][2], lane & 28);
        const float ilo = 1.f / (zlo + 1e-6f);
        const float ihi = 1.f / (zhi + 1e-6f);
        const int rlo = rbase[ms];
        float* olo = out + ((size_t)bh * SEQ + (size_t)ch * CS + rlo) * DV;
        float* ohi = olo + 8 * DV;
#pragma unroll
        for (int nt = 0; nt < 8; nt++) {
            const int col = nt * 8 + 2 * qc;
            *(float2*)(olo + col) = make_float2(O[ms][nt][0] * ilo, O[ms][nt][1] * ilo);
            *(float2*)(ohi + col) = make_float2(O[ms][nt][2] * ihi, O[ms][nt][3] * ihi);
        }
    }
}

// ---------------------------------------------------------------------------
extern "C" void kernel_launch(void* const* d_in, const int* in_sizes, int n_in,
                              void* d_out, int out_size)
{
    const float* q = (const float*)d_in[0];
    const float* k = (const float*)d_in[1];
    const float* v = (const float*)d_in[2];
    float* out = (float*)d_out;

    const int smem1 = 17408 + 2 * 36864;                                  // 91136 B
    const int smem3 = (2*5184 + 2*9216 + 4*2048 + 2*648) * 4 + 17408;     // 170560 B
    cudaFuncSetAttribute(k1_sums,   cudaFuncAttributeMaxDynamicSharedMemorySize, smem1);
    cudaFuncSetAttribute(k3_output, cudaFuncAttributeMaxDynamicSharedMemorySize, smem3);

    dim3 grid(BH, NCH);
    k1_sums<<<grid, 288, smem1>>>(k, v);
    k2_prefix<<<dim3(BH, 12), 256>>>();
    k3_output<<<grid, 256, smem3>>>(q, k, v, out);
}

// round 10
// speedup vs baseline: 2.7174x; 1.0242x over previous
#include <cuda_runtime.h>
#include <cuda_bf16.h>
#include <cstdint>

#define BH   32
#define NCH  16
#define CS   256
#define D    16
#define DV   64
#define SEQ  4096
#define NPP  144     // 136 (d<=e) pairs padded to 144

// state per (bh,chunk): KKVsym[144][72], KVext[16][72], Vsum[72]
#define ST_KV   10368
#define ST_V    11520
#define ST_SIZE 11592

__device__ float g_state[(size_t)BH * NCH * ST_SIZE];   // ~23.7 MB scratch

// ---- pair table (d<=e), constexpr-initialized constant memory -------------
struct PairTab { unsigned char d[NPP]; unsigned char e[NPP]; float cw[NPP]; };
__host__ __device__ constexpr PairTab mk_tab() {
    PairTab t{};
    int p = 0;
    for (int d = 0; d < 16; d++)
        for (int e = d; e < 16; e++) {
            t.d[p] = (unsigned char)d; t.e[p] = (unsigned char)e;
            t.cw[p] = (d == e) ? 0.5f : 1.0f; p++;
        }
    for (; p < NPP; p++) { t.d[p] = 0; t.e[p] = 0; t.cw[p] = 0.f; }
    return t;
}
__constant__ PairTab cPT = mk_tab();

// ---------------------------------------------------------------------------
__device__ __forceinline__ void split_pack(float a, float b, uint32_t& hi, uint32_t& lo) {
    uint32_t h;
    asm("cvt.rn.bf16x2.f32 %0, %1, %2;" : "=r"(h) : "f"(b), "f"(a));
    const float ah = __uint_as_float(h << 16);
    const float bh = __uint_as_float(h & 0xffff0000u);
    uint32_t l;
    asm("cvt.rn.bf16x2.f32 %0, %1, %2;" : "=r"(l) : "f"(b - bh), "f"(a - ah));
    hi = h; lo = l;
}
__device__ __forceinline__ void unpack_bf(uint32_t w, float& a, float& b) {
    a = __uint_as_float(w << 16);
    b = __uint_as_float(w & 0xffff0000u);
}
__device__ __forceinline__ void mma16816(float c[4], const uint32_t a[4],
                                         uint32_t b0, uint32_t b1) {
    asm volatile(
        "mma.sync.aligned.m16n8k16.row.col.f32.bf16.bf16.f32 "
        "{%0,%1,%2,%3}, {%4,%5,%6,%7}, {%8,%9}, {%0,%1,%2,%3};\n"
        : "+f"(c[0]), "+f"(c[1]), "+f"(c[2]), "+f"(c[3])
        : "r"(a[0]), "r"(a[1]), "r"(a[2]), "r"(a[3]), "r"(b0), "r"(b1));
}

// ---------------------------------------------------------------------------
// K1: KKVsym[144,72] = W[pair,c] @ Vext[c,72]  (Vext col64 = 1)
//     KVext[16,72]   = K^T @ Vext   (MMA, n-tiles across warps)
//     Vsum[72]       = column sums (SIMT + shfl)
// 288 threads = 9 warps; warp w owns m-tile w of the 144-row GEMM.
// ---------------------------------------------------------------------------
__global__ __launch_bounds__(288, 2) void k1_sums(
    const float* __restrict__ k, const float* __restrict__ v)
{
    extern __shared__ char smem[];
    float*    sK  = (float*)smem;                       // 256*17 floats
    uint32_t* sVh = (uint32_t*)(smem + 17408);          // 128*72
    uint32_t* sVl = sVh + 9216;                         // 128*72

    const int bh = blockIdx.x, ch = blockIdx.y;
    const int tid = threadIdx.x, lane = tid & 31, w = tid >> 5;
    const int qr = lane >> 2, qc = lane & 3;
    const float* kb = k + ((size_t)bh * SEQ + (size_t)ch * CS) * D;
    const float* vb = v + ((size_t)bh * SEQ + (size_t)ch * CS) * DV;

    for (int i = tid; i < CS * D; i += 288) sK[(i >> 4) * 17 + (i & 15)] = kb[i];
    for (int i = tid; i < 128 * 72; i += 288) {
        const int cp = i / 72, f = i - cp * 72;
        float v0, v1;
        if (f < 64)       { v0 = vb[cp * 128 + f]; v1 = vb[cp * 128 + 64 + f]; }
        else if (f == 64) { v0 = 1.f; v1 = 1.f; }
        else              { v0 = 0.f; v1 = 0.f; }
        split_pack(v0, v1, sVh[i], sVl[i]);
    }
    __syncthreads();

    const int p0 = w * 16 + qr, p1 = p0 + 8;
    const int d0 = cPT.d[p0], e0 = cPT.e[p0];
    const int d1 = cPT.d[p1], e1 = cPT.e[p1];

    float acc[9][4];
#pragma unroll
    for (int nt = 0; nt < 9; nt++)
#pragma unroll
        for (int j = 0; j < 4; j++) acc[nt][j] = 0.f;

    for (int ks = 0; ks < 16; ks++) {
        const int cA = ks * 16 + 2 * qc, cB = cA + 1, cC = cA + 8, cD = cA + 9;
        const float* rA = sK + cA * 17; const float* rB = sK + cB * 17;
        const float* rC = sK + cC * 17; const float* rD = sK + cD * 17;
        uint32_t Ah[4], Al[4];
        split_pack(rA[d0] * rA[e0], rB[d0] * rB[e0], Ah[0], Al[0]);
        split_pack(rA[d1] * rA[e1], rB[d1] * rB[e1], Ah[1], Al[1]);
        split_pack(rC[d0] * rC[e0], rD[d0] * rD[e0], Ah[2], Al[2]);
        split_pack(rC[d1] * rC[e1], rD[d1] * rD[e1], Ah[3], Al[3]);

        const int b0i = (ks * 8 + qc) * 72 + qr, b1i = b0i + 288;
#pragma unroll
        for (int nt = 0; nt < 9; nt++) {
            const uint32_t bh0 = sVh[b0i + nt * 8], bh1 = sVh[b1i + nt * 8];
            const uint32_t bl0 = sVl[b0i + nt * 8], bl1 = sVl[b1i + nt * 8];
            mma16816(acc[nt], Ah, bh0, bh1);
            mma16816(acc[nt], Ah, bl0, bl1);
            mma16816(acc[nt], Al, bh0, bh1);
        }
    }

    float* st = g_state + (size_t)(bh * NCH + ch) * ST_SIZE;
#pragma unroll
    for (int nt = 0; nt < 9; nt++) {
        const int col = nt * 8 + 2 * qc;
        *(float2*)(st + p0 * 72 + col) = make_float2(acc[nt][0], acc[nt][1]);
        *(float2*)(st + p1 * 72 + col) = make_float2(acc[nt][2], acc[nt][3]);
    }

    // ---- KVext[16,72] = K^T @ Vext : warp w computes n-tile w ----
    {
        float kv[4] = {0.f, 0.f, 0.f, 0.f};
        for (int ks = 0; ks < 16; ks++) {
            const int cA = ks * 16 + 2 * qc, cB = cA + 1, cC = cA + 8, cD = cA + 9;
            uint32_t Ah[4], Al[4];
            split_pack(sK[cA * 17 + qr],     sK[cB * 17 + qr],     Ah[0], Al[0]);
            split_pack(sK[cA * 17 + qr + 8], sK[cB * 17 + qr + 8], Ah[1], Al[1]);
            split_pack(sK[cC * 17 + qr],     sK[cD * 17 + qr],     Ah[2], Al[2]);
            split_pack(sK[cC * 17 + qr + 8], sK[cD * 17 + qr + 8], Ah[3], Al[3]);
            const int b0i = (ks * 8 + qc) * 72 + w * 8 + qr, b1i = b0i + 288;
            const uint32_t bh0 = sVh[b0i], bh1 = sVh[b1i];
            const uint32_t bl0 = sVl[b0i], bl1 = sVl[b1i];
            mma16816(kv, Ah, bh0, bh1);
            mma16816(kv, Ah, bl0, bl1);
            mma16816(kv, Al, bh0, bh1);
        }
        const int col = w * 8 + 2 * qc;
        *(float2*)(st + ST_KV + qr * 72 + col)       = make_float2(kv[0], kv[1]);
        *(float2*)(st + ST_KV + (qr + 8) * 72 + col) = make_float2(kv[2], kv[3]);
    }

    // ---- Vsum[72] : 4 threads per column + shfl reduce ----
    {
        const int f = tid >> 2, qt = tid & 3;
        float s = 0.f;
#pragma unroll 4
        for (int r = qt * 32; r < qt * 32 + 32; r++) {
            float a, b, c, d2;
            unpack_bf(sVh[r * 72 + f], a, b);
            unpack_bf(sVl[r * 72 + f], c, d2);
            s += (a + c) + (b + d2);
        }
        s += __shfl_xor_sync(0xffffffffu, s, 1);
        s += __shfl_xor_sync(0xffffffffu, s, 2);
        if (qt == 0) st[ST_V + f] = s;
    }
}

// ---------------------------------------------------------------------------
// K2: exclusive prefix over chunk axis
// ---------------------------------------------------------------------------
__global__ __launch_bounds__(256) void k2_prefix()
{
    const int bh = blockIdx.x;
    int idx = blockIdx.y * 256 + threadIdx.x;
    const int stride = gridDim.y * 256;
    float* base = g_state + (size_t)bh * NCH * ST_SIZE;
    for (; idx < ST_SIZE; idx += stride) {
        float run = 0.f;
#pragma unroll
        for (int c = 0; c < NCH; c++) {
            float* p = base + (size_t)c * ST_SIZE + idx;
            const float t = *p; *p = run; run += t;
        }
    }
}

// ---------------------------------------------------------------------------
// K3: O[256,72] = Wq_sym @ KKVsym + [qhat|1] @ [KVext;Vsumrow] + A_intra @ Vext
// col 64 of O accumulates z (Vsum[64] = prefixed token count).
// 512 threads = 16 warps, ONE 16-row m-tile per warp. SMSP-balanced tiles:
// SMSP s gets tiles {s, 7-s, 8+s, 15-s} (su-step sums = 34 each).
// ---------------------------------------------------------------------------
__global__ __launch_bounds__(512) void k3_output(
    const float* __restrict__ q, const float* __restrict__ k,
    const float* __restrict__ v, float* __restrict__ out)
{
    extern __shared__ char smem[];
    uint32_t* sSth = (uint32_t*)smem;        // 5184  KKVsym hi (pair-pair major)
    uint32_t* sStl = sSth + 5184;            // 5184
    uint32_t* sVh  = sStl + 5184;            // 9216  Vext hi
    uint32_t* sVl  = sVh  + 9216;            // 9216
    uint32_t* sKph = sVl  + 9216;            // 2048  k pair-major [d/2][s]
    uint32_t* sKpl = sKph + 2048;
    uint32_t* sQh  = sKpl + 2048;            // 2048  qhat pair-major [t][d/2]
    uint32_t* sQl  = sQh  + 2048;
    uint32_t* sLh  = sQl  + 2048;            // 648   [KVext;Vsumrow;0]
    uint32_t* sLl  = sLh  + 648;
    float*    sQ   = (float*)(sLl + 648);    // 256*17 fp32 qhat

    const int bh = blockIdx.x, ch = blockIdx.y;
    const int tid = threadIdx.x, lane = tid & 31, wid = tid >> 5;
    const int qr = lane >> 2, qc = lane & 3;
    const float* qb = q + ((size_t)bh * SEQ + (size_t)ch * CS) * D;
    const float* kb = k + ((size_t)bh * SEQ + (size_t)ch * CS) * D;
    const float* vb = v + ((size_t)bh * SEQ + (size_t)ch * CS) * DV;
    const float* st = g_state + (size_t)(bh * NCH + ch) * ST_SIZE;

    for (int w = tid; w < 2048; w += 512) {
        {   // qhat pairs + fp32 copy
            float2 qv = ((const float2*)qb)[w];
            const float x = qv.x * 0.25f, y = qv.y * 0.25f;
            split_pack(x, y, sQh[w], sQl[w]);
            const int t = w >> 3, dp = w & 7;
            sQ[t * 17 + 2 * dp] = x;  sQ[t * 17 + 2 * dp + 1] = y;
        }
        {   // k pairs along d: word[(d/2)*256 + s]
            const int s = w & 255, dpp = w >> 8;
            float2 kv2 = ((const float2*)kb)[s * 8 + dpp];
            split_pack(kv2.x, kv2.y, sKph[w], sKpl[w]);
        }
    }
    for (int w = tid; w < 9216; w += 512) {
        const int dep = w / 72, f = w - dep * 72;
        float v0, v1;
        if (f < 64)       { v0 = vb[dep * 128 + f]; v1 = vb[dep * 128 + 64 + f]; }
        else if (f == 64) { v0 = 1.f; v1 = 1.f; }
        else              { v0 = 0.f; v1 = 0.f; }
        split_pack(v0, v1, sVh[w], sVl[w]);
        if (w < 5184)
            split_pack(st[(2 * dep) * 72 + f], st[(2 * dep + 1) * 72 + f], sSth[w], sStl[w]);
    }
    for (int w = tid; w < 648; w += 512) {
        const int kp = w / 72, f = w - kp * 72;
        float a, b;
        if (kp < 8) {
            a = st[ST_KV + (2 * kp) * 72 + f];
            b = st[ST_KV + (2 * kp + 1) * 72 + f];
        } else {   // row 16 = prefixed Vsum (col64 = token count), row 17 = 0
            a = st[ST_V + f];
            b = 0.f;
        }
        split_pack(a, b, sLh[w], sLl[w]);
    }
    __syncthreads();

    // SMSP-balanced tile assignment
    const int g = wid >> 2, s4 = wid & 3;
    const int tb = (g == 0) ? s4 : (g == 1) ? 7 - s4 : (g == 2) ? 8 + s4 : 15 - s4;
    const int rbase = tb * 16 + qr;

    float O[9][4];
#pragma unroll
    for (int nt = 0; nt < 9; nt++)
#pragma unroll
        for (int j = 0; j < 4; j++) O[nt][j] = 0.f;

    // ---- part 1: Wq_sym[t,p] = cw_p * q_d(p) * q_e(p)  @  KKVsym ----
    for (int ks = 0; ks < 9; ks++) {
        const int pA = ks * 16 + 2 * qc, pB = pA + 1, pC = pA + 8, pD = pA + 9;
        const int dA = cPT.d[pA], eA = cPT.e[pA]; const float wA = cPT.cw[pA];
        const int dB = cPT.d[pB], eB = cPT.e[pB]; const float wB = cPT.cw[pB];
        const int dC = cPT.d[pC], eC = cPT.e[pC]; const float wC = cPT.cw[pC];
        const int dD = cPT.d[pD], eD = cPT.e[pD]; const float wD = cPT.cw[pD];

        const float* qlo = sQ + rbase * 17;
        const float* qhi = qlo + 8 * 17;
        uint32_t Ah[4], Al[4];
        split_pack(wA * qlo[dA] * qlo[eA], wB * qlo[dB] * qlo[eB], Ah[0], Al[0]);
        split_pack(wA * qhi[dA] * qhi[eA], wB * qhi[dB] * qhi[eB], Ah[1], Al[1]);
        split_pack(wC * qlo[dC] * qlo[eC], wD * qlo[dD] * qlo[eD], Ah[2], Al[2]);
        split_pack(wC * qhi[dC] * qhi[eC], wD * qhi[dD] * qhi[eD], Ah[3], Al[3]);

        const int b0i = (ks * 8 + qc) * 72 + qr, b1i = b0i + 288;
#pragma unroll
        for (int nt = 0; nt < 9; nt++) {
            const uint32_t bh0 = sSth[b0i + nt * 8], bh1 = sSth[b1i + nt * 8];
            const uint32_t bl0 = sStl[b0i + nt * 8], bl1 = sStl[b1i + nt * 8];
            mma16816(O[nt], Ah, bh0, bh1);
            mma16816(O[nt], Ah, bl0, bl1);
            mma16816(O[nt], Al, bh0, bh1);
        }
    }

    // q A-fragments (linear part + S MMAs)
    uint32_t Aq_h[4], Aq_l[4];
    {
        const int rlo = rbase, rhi = rlo + 8;
        Aq_h[0] = sQh[rlo * 8 + qc];     Aq_l[0] = sQl[rlo * 8 + qc];
        Aq_h[1] = sQh[rhi * 8 + qc];     Aq_l[1] = sQl[rhi * 8 + qc];
        Aq_h[2] = sQh[rlo * 8 + qc + 4]; Aq_l[2] = sQl[rlo * 8 + qc + 4];
        Aq_h[3] = sQh[rhi * 8 + qc + 4]; Aq_l[3] = sQl[rhi * 8 + qc + 4];
    }

    // ---- part 2: linear (qhat @ KVext) + const row (Vsum_prev incl. count) ----
    {
        const int b0i = qc * 72 + qr, b1i = b0i + 288;
        const uint32_t onesA = (qc == 0) ? 0x00003F80u : 0u;   // bf16 1.0 low half
        const uint32_t Ac[4] = { onesA, onesA, 0u, 0u };
#pragma unroll
        for (int nt = 0; nt < 9; nt++) {
            const uint32_t bh0 = sLh[b0i + nt * 8], bh1 = sLh[b1i + nt * 8];
            const uint32_t bl0 = sLl[b0i + nt * 8], bl1 = sLl[b1i + nt * 8];
            const uint32_t cb_h = (qc == 0) ? sLh[576 + nt * 8 + qr] : 0u;
            const uint32_t cb_l = (qc == 0) ? sLl[576 + nt * 8 + qr] : 0u;
            mma16816(O[nt], Aq_h, bh0, bh1);
            mma16816(O[nt], Aq_h, bl0, bl1);
            mma16816(O[nt], Aq_l, bh0, bh1);
            mma16816(O[nt], Ac, cb_h, 0u);
            mma16816(O[nt], Ac, cb_l, 0u);
        }
    }

    // ---- part 3: intra-chunk causal A = tril(1+S+0.5S^2), fused ----
    {
        const int sulim = tb;
        for (int su = 0; su <= sulim; su++) {
            const int sbase = su * 16;
            float s0[4] = {0.f, 0.f, 0.f, 0.f};
            float s1[4] = {0.f, 0.f, 0.f, 0.f};
            const int bk0 = qc * 256 + sbase + qr;
            const int bk1 = bk0 + 1024;
            mma16816(s0, Aq_h, sKph[bk0], sKph[bk1]);
            mma16816(s0, Aq_h, sKpl[bk0], sKpl[bk1]);
            mma16816(s0, Aq_l, sKph[bk0], sKph[bk1]);
            mma16816(s1, Aq_h, sKph[bk0 + 8], sKph[bk1 + 8]);
            mma16816(s1, Aq_h, sKpl[bk0 + 8], sKpl[bk1 + 8]);
            mma16816(s1, Aq_l, sKph[bk0 + 8], sKph[bk1 + 8]);

            const int rlo = rbase, rhi = rlo + 8;
            const int c0 = sbase + 2 * qc;
            float a00 = (c0     <= rlo) ? fmaf(0.5f * s0[0], s0[0], 1.f + s0[0]) : 0.f;
            float a01 = (c0 + 1 <= rlo) ? fmaf(0.5f * s0[1], s0[1], 1.f + s0[1]) : 0.f;
            float a10 = (c0     <= rhi) ? fmaf(0.5f * s0[2], s0[2], 1.f + s0[2]) : 0.f;
            float a11 = (c0 + 1 <= rhi) ? fmaf(0.5f * s0[3], s0[3], 1.f + s0[3]) : 0.f;
            float a20 = (c0 + 8 <= rlo) ? fmaf(0.5f * s1[0], s1[0], 1.f + s1[0]) : 0.f;
            float a21 = (c0 + 9 <= rlo) ? fmaf(0.5f * s1[1], s1[1], 1.f + s1[1]) : 0.f;
            float a30 = (c0 + 8 <= rhi) ? fmaf(0.5f * s1[2], s1[2], 1.f + s1[2]) : 0.f;
            float a31 = (c0 + 9 <= rhi) ? fmaf(0.5f * s1[3], s1[3], 1.f + s1[3]) : 0.f;

            uint32_t AH[4], AL[4];
            split_pack(a00, a01, AH[0], AL[0]);
            split_pack(a10, a11, AH[1], AL[1]);
            split_pack(a20, a21, AH[2], AL[2]);
            split_pack(a30, a31, AH[3], AL[3]);

            const int vb0 = ((sbase >> 1) + qc) * 72 + qr;
            const int vb1 = vb0 + 288;
#pragma unroll
            for (int nt = 0; nt < 9; nt++) {
                const uint32_t bh0 = sVh[vb0 + nt * 8], bh1 = sVh[vb1 + nt * 8];
                const uint32_t bl0 = sVl[vb0 + nt * 8], bl1 = sVl[vb1 + nt * 8];
                mma16816(O[nt], AH, bh0, bh1);
                mma16816(O[nt], AH, bl0, bl1);
                mma16816(O[nt], AL, bh0, bh1);
            }
        }
    }

    // ---- epilogue: z = col 64, divide, store ----
    {
        const float zlo = __shfl_sync(0xffffffffu, O[8][0], lane & 28);
        const float zhi = __shfl_sync(0xffffffffu, O[8][2], lane & 28);
        const float ilo = 1.f / (zlo + 1e-6f);
        const float ihi = 1.f / (zhi + 1e-6f);
        float* olo = out + ((size_t)bh * SEQ + (size_t)ch * CS + rbase) * DV;
        float* ohi = olo + 8 * DV;
#pragma unroll
        for (int nt = 0; nt < 8; nt++) {
            const int col = nt * 8 + 2 * qc;
            *(float2*)(olo + col) = make_float2(O[nt][0] * ilo, O[nt][1] * ilo);
            *(float2*)(ohi + col) = make_float2(O[nt][2] * ihi, O[nt][3] * ihi);
        }
    }
}

// ---------------------------------------------------------------------------
extern "C" void kernel_launch(void* const* d_in, const int* in_sizes, int n_in,
                              void* d_out, int out_size)
{
    const float* q = (const float*)d_in[0];
    const float* k = (const float*)d_in[1];
    const float* v = (const float*)d_in[2];
    float* out = (float*)d_out;

    const int smem1 = 17408 + 2 * 36864;                                  // 91136 B
    const int smem3 = (2*5184 + 2*9216 + 4*2048 + 2*648) * 4 + 17408;     // 170560 B
    cudaFuncSetAttribute(k1_sums,   cudaFuncAttributeMaxDynamicSharedMemorySize, smem1);
    cudaFuncSetAttribute(k3_output, cudaFuncAttributeMaxDynamicSharedMemorySize, smem3);

    dim3 grid(BH, NCH);
    k1_sums<<<grid, 288, smem1>>>(k, v);
    k2_prefix<<<dim3(BH, 12), 256>>>();
    k3_output<<<grid, 512, smem3>>>(q, k, v, out);
}

// round 14
// speedup vs baseline: 2.8515x; 1.0494x over previous
#include <cuda_runtime.h>
#include <cuda_bf16.h>
#include <cstdint>

#define BH   32
#define NCH  16
#define CS   256
#define D    16
#define DV   64
#define SEQ  4096
#define NPP  144     // 136 (d<=e) pairs padded to 144

// state per (bh,chunk): KKVsym[144][72], KVext[16][72], Vsum[72]
#define ST_KV   10368
#define ST_V    11520
#define ST_SIZE 11592

__device__ float g_state[(size_t)BH * NCH * ST_SIZE];   // ~23.7 MB scratch

// ---- pair table (d<=e), constexpr-initialized constant memory -------------
struct PairTab { unsigned char d[NPP]; unsigned char e[NPP]; float cw[NPP]; };
__host__ __device__ constexpr PairTab mk_tab() {
    PairTab t{};
    int p = 0;
    for (int d = 0; d < 16; d++)
        for (int e = d; e < 16; e++) {
            t.d[p] = (unsigned char)d; t.e[p] = (unsigned char)e;
            t.cw[p] = (d == e) ? 0.5f : 1.0f; p++;
        }
    for (; p < NPP; p++) { t.d[p] = 0; t.e[p] = 0; t.cw[p] = 0.f; }
    return t;
}
__constant__ PairTab cPT = mk_tab();

// ---------------------------------------------------------------------------
__device__ __forceinline__ void split_pack(float a, float b, uint32_t& hi, uint32_t& lo) {
    uint32_t h;
    asm("cvt.rn.bf16x2.f32 %0, %1, %2;" : "=r"(h) : "f"(b), "f"(a));
    const float ah = __uint_as_float(h << 16);
    const float bh = __uint_as_float(h & 0xffff0000u);
    uint32_t l;
    asm("cvt.rn.bf16x2.f32 %0, %1, %2;" : "=r"(l) : "f"(b - bh), "f"(a - ah));
    hi = h; lo = l;
}
__device__ __forceinline__ void unpack_bf(uint32_t w, float& a, float& b) {
    a = __uint_as_float(w << 16);
    b = __uint_as_float(w & 0xffff0000u);
}
__device__ __forceinline__ void mma16816(float c[4], const uint32_t a[4],
                                         uint32_t b0, uint32_t b1) {
    asm volatile(
        "mma.sync.aligned.m16n8k16.row.col.f32.bf16.bf16.f32 "
        "{%0,%1,%2,%3}, {%4,%5,%6,%7}, {%8,%9}, {%0,%1,%2,%3};\n"
        : "+f"(c[0]), "+f"(c[1]), "+f"(c[2]), "+f"(c[3])
        : "r"(a[0]), "r"(a[1]), "r"(a[2]), "r"(a[3]), "r"(b0), "r"(b1));
}
// One ldmatrix.x4 = {b0_hi, b1_hi, b0_lo, b1_lo} for a 16k x 8n tile.
__device__ __forceinline__ void ldsm_x4(uint32_t& a, uint32_t& b,
                                        uint32_t& c, uint32_t& d, uint32_t saddr) {
    asm volatile("ldmatrix.sync.aligned.m8n8.x4.shared.b16 {%0,%1,%2,%3}, [%4];"
                 : "=r"(a), "=r"(b), "=r"(c), "=r"(d) : "r"(saddr));
}
// tile layout: per (blk, nt): 4 matrices x 8 rows x 16B = 512B.
// matrix m: {0: hi kp0-3, 1: hi kp4-7, 2: lo kp0-3, 3: lo kp4-7}; row = n, word = kp&3.
__device__ __forceinline__ int tile_word(int blk9nt, int mat, int row, int j) {
    return (blk9nt * 4 + mat) * 32 + row * 4 + j;
}
__device__ __forceinline__ uint32_t tile_addr(uint32_t base_s, int blk9nt, int lane) {
    return base_s + (uint32_t)((blk9nt * 4 + (lane >> 3)) << 7) + (uint32_t)((lane & 7) << 4);
}

// ---------------------------------------------------------------------------
// K1: KKVsym[144,72] = W[pair,c] @ Vext[c,72]  (Vext col64 = 1)
//     KVext[16,72]   = K^T @ Vext   (MMA, n-tiles across warps)
//     Vsum[72]       = column sums (SIMT + shfl)
// 288 threads = 9 warps; warp w owns m-tile w of the 144-row GEMM.
// B operands (V) stored as ldmatrix tiles.
// ---------------------------------------------------------------------------
__global__ __launch_bounds__(288, 2) void k1_sums(
    const float* __restrict__ k, const float* __restrict__ v)
{
    extern __shared__ char smem[];
    float*    sK  = (float*)smem;                       // 256*17 floats (17408 B)
    uint32_t* sV2 = (uint32_t*)(smem + 17408);          // 16ks*9nt*128 words (73728 B)
    const uint32_t sV2s = (uint32_t)__cvta_generic_to_shared(sV2);

    const int bh = blockIdx.x, ch = blockIdx.y;
    const int tid = threadIdx.x, lane = tid & 31, w = tid >> 5;
    const int qr = lane >> 2, qc = lane & 3;
    const float* kb = k + ((size_t)bh * SEQ + (size_t)ch * CS) * D;
    const float* vb = v + ((size_t)bh * SEQ + (size_t)ch * CS) * DV;

    for (int i = tid; i < CS * D; i += 288) sK[(i >> 4) * 17 + (i & 15)] = kb[i];
    for (int i = tid; i < 128 * 72; i += 288) {
        const int cp = i / 72, f = i - cp * 72;
        float v0, v1;
        if (f < 64)       { v0 = vb[cp * 128 + f]; v1 = vb[cp * 128 + 64 + f]; }
        else if (f == 64) { v0 = 1.f; v1 = 1.f; }
        else              { v0 = 0.f; v1 = 0.f; }
        uint32_t hi, lo;
        split_pack(v0, v1, hi, lo);
        const int ks = cp >> 3, kp8 = cp & 7;
        const int idx = tile_word(ks * 9 + (f >> 3), kp8 >> 2, f & 7, kp8 & 3);
        sV2[idx] = hi; sV2[idx + 64] = lo;
    }
    __syncthreads();

    const int p0 = w * 16 + qr, p1 = p0 + 8;
    const int d0 = cPT.d[p0], e0 = cPT.e[p0];
    const int d1 = cPT.d[p1], e1 = cPT.e[p1];

    float acc[9][4];
#pragma unroll
    for (int nt = 0; nt < 9; nt++)
#pragma unroll
        for (int j = 0; j < 4; j++) acc[nt][j] = 0.f;

    for (int ks = 0; ks < 16; ks++) {
        const int cA = ks * 16 + 2 * qc, cB = cA + 1, cC = cA + 8, cD = cA + 9;
        const float* rA = sK + cA * 17; const float* rB = sK + cB * 17;
        const float* rC = sK + cC * 17; const float* rD = sK + cD * 17;
        uint32_t Ah[4], Al[4];
        split_pack(rA[d0] * rA[e0], rB[d0] * rB[e0], Ah[0], Al[0]);
        split_pack(rA[d1] * rA[e1], rB[d1] * rB[e1], Ah[1], Al[1]);
        split_pack(rC[d0] * rC[e0], rD[d0] * rD[e0], Ah[2], Al[2]);
        split_pack(rC[d1] * rC[e1], rD[d1] * rD[e1], Ah[3], Al[3]);

#pragma unroll
        for (int nt = 0; nt < 9; nt++) {
            uint32_t bh0, bh1, bl0, bl1;
            ldsm_x4(bh0, bh1, bl0, bl1, tile_addr(sV2s, ks * 9 + nt, lane));
            mma16816(acc[nt], Ah, bh0, bh1);
            mma16816(acc[nt], Ah, bl0, bl1);
            mma16816(acc[nt], Al, bh0, bh1);
        }
    }

    float* st = g_state + (size_t)(bh * NCH + ch) * ST_SIZE;
#pragma unroll
    for (int nt = 0; nt < 9; nt++) {
        const int col = nt * 8 + 2 * qc;
        *(float2*)(st + p0 * 72 + col) = make_float2(acc[nt][0], acc[nt][1]);
        *(float2*)(st + p1 * 72 + col) = make_float2(acc[nt][2], acc[nt][3]);
    }

    // ---- KVext[16,72] = K^T @ Vext : warp w computes n-tile w ----
    {
        float kv[4] = {0.f, 0.f, 0.f, 0.f};
        for (int ks = 0; ks < 16; ks++) {
            const int cA = ks * 16 + 2 * qc, cB = cA + 1, cC = cA + 8, cD = cA + 9;
            uint32_t Ah[4], Al[4];
            split_pack(sK[cA * 17 + qr],     sK[cB * 17 + qr],     Ah[0], Al[0]);
            split_pack(sK[cA * 17 + qr + 8], sK[cB * 17 + qr + 8], Ah[1], Al[1]);
            split_pack(sK[cC * 17 + qr],     sK[cD * 17 + qr],     Ah[2], Al[2]);
            split_pack(sK[cC * 17 + qr + 8], sK[cD * 17 + qr + 8], Ah[3], Al[3]);
            uint32_t bh0, bh1, bl0, bl1;
            ldsm_x4(bh0, bh1, bl0, bl1, tile_addr(sV2s, ks * 9 + w, lane));
            mma16816(kv, Ah, bh0, bh1);
            mma16816(kv, Ah, bl0, bl1);
            mma16816(kv, Al, bh0, bh1);
        }
        const int col = w * 8 + 2 * qc;
        *(float2*)(st + ST_KV + qr * 72 + col)       = make_float2(kv[0], kv[1]);
        *(float2*)(st + ST_KV + (qr + 8) * 72 + col) = make_float2(kv[2], kv[3]);
    }

    // ---- Vsum[72] : 4 threads per column + shfl reduce ----
    {
        const int f = tid >> 2, qt = tid & 3;
        const int nt = f >> 3, row = f & 7;
        float s = 0.f;
#pragma unroll 4
        for (int r = qt * 32; r < qt * 32 + 32; r++) {
            const int ks = r >> 3, kp8 = r & 7;
            const int idx = tile_word(ks * 9 + nt, kp8 >> 2, row, kp8 & 3);
            float a, b, c, d2;
            unpack_bf(sV2[idx], a, b);
            unpack_bf(sV2[idx + 64], c, d2);
            s += (a + c) + (b + d2);
        }
        s += __shfl_xor_sync(0xffffffffu, s, 1);
        s += __shfl_xor_sync(0xffffffffu, s, 2);
        if (qt == 0) st[ST_V + f] = s;
    }
}

// ---------------------------------------------------------------------------
// K2: exclusive prefix over chunk axis
// ---------------------------------------------------------------------------
__global__ __launch_bounds__(256) void k2_prefix()
{
    const int bh = blockIdx.x;
    int idx = blockIdx.y * 256 + threadIdx.x;
    const int stride = gridDim.y * 256;
    float* base = g_state + (size_t)bh * NCH * ST_SIZE;
    for (; idx < ST_SIZE; idx += stride) {
        float run = 0.f;
#pragma unroll
        for (int c = 0; c < NCH; c++) {
            float* p = base + (size_t)c * ST_SIZE + idx;
            const float t = *p; *p = run; run += t;
        }
    }
}

// ---------------------------------------------------------------------------
// K3: O[256,72] = Wq_sym @ KKVsym + [qhat|1] @ [KVext;Vsumrow] + A_intra @ Vext
// col 64 of O accumulates z (Vsum[64] = prefixed token count).
// 512 threads = 16 warps, ONE 16-row m-tile per warp, SMSP-balanced.
// All B operands via ldmatrix tiles.
// ---------------------------------------------------------------------------
__global__ __launch_bounds__(512) void k3_output(
    const float* __restrict__ q, const float* __restrict__ k,
    const float* __restrict__ v, float* __restrict__ out)
{
    extern __shared__ char smem[];
    uint32_t* sSt2 = (uint32_t*)smem;        // 10368 words: KKVsym tiles (9ks x 9nt)
    uint32_t* sV2  = sSt2 + 10368;           // 18432 words: Vext tiles (16ks x 9nt)
    uint32_t* sK2  = sV2  + 18432;           // 4096 words:  K-pair tiles (16su x 2stile)
    uint32_t* sQh  = sK2  + 4096;            // 2048  qhat pair-major [t][d/2]
    uint32_t* sQl  = sQh  + 2048;
    uint32_t* sLh  = sQl  + 2048;            // 648   [KVext;Vsumrow;0]
    uint32_t* sLl  = sLh  + 648;
    float*    sQ   = (float*)(sLl + 648);    // 256*17 fp32 qhat
    const uint32_t sSt2s = (uint32_t)__cvta_generic_to_shared(sSt2);
    const uint32_t sV2s  = (uint32_t)__cvta_generic_to_shared(sV2);
    const uint32_t sK2s  = (uint32_t)__cvta_generic_to_shared(sK2);

    const int bh = blockIdx.x, ch = blockIdx.y;
    const int tid = threadIdx.x, lane = tid & 31, wid = tid >> 5;
    const int qr = lane >> 2, qc = lane & 3;
    const float* qb = q + ((size_t)bh * SEQ + (size_t)ch * CS) * D;
    const float* kb = k + ((size_t)bh * SEQ + (size_t)ch * CS) * D;
    const float* vb = v + ((size_t)bh * SEQ + (size_t)ch * CS) * DV;
    const float* st = g_state + (size_t)(bh * NCH + ch) * ST_SIZE;

    for (int w = tid; w < 2048; w += 512) {
        {   // qhat pairs + fp32 copy
            float2 qv = ((const float2*)qb)[w];
            const float x = qv.x * 0.25f, y = qv.y * 0.25f;
            split_pack(x, y, sQh[w], sQl[w]);
            const int t = w >> 3, dp = w & 7;
            sQ[t * 17 + 2 * dp] = x;  sQ[t * 17 + 2 * dp + 1] = y;
        }
        {   // k pairs along d -> ldmatrix tiles (su, stile)
            const int s = w & 255, dpp = w >> 8;
            float2 kv2 = ((const float2*)kb)[s * 8 + dpp];
            uint32_t hi, lo;
            split_pack(kv2.x, kv2.y, hi, lo);
            const int idx = tile_word((s >> 4) * 2 + ((s >> 3) & 1), dpp >> 2, s & 7, dpp & 3);
            sK2[idx] = hi; sK2[idx + 64] = lo;
        }
    }
    for (int w = tid; w < 9216; w += 512) {
        const int cp = w / 72, f = w - cp * 72;
        const int nt = f >> 3, row = f & 7;
        {   // Vext tiles
            float v0, v1;
            if (f < 64)       { v0 = vb[cp * 128 + f]; v1 = vb[cp * 128 + 64 + f]; }
            else if (f == 64) { v0 = 1.f; v1 = 1.f; }
            else              { v0 = 0.f; v1 = 0.f; }
            uint32_t hi, lo;
            split_pack(v0, v1, hi, lo);
            const int ks = cp >> 3, kp8 = cp & 7;
            const int idx = tile_word(ks * 9 + nt, kp8 >> 2, row, kp8 & 3);
            sV2[idx] = hi; sV2[idx + 64] = lo;
        }
        if (w < 5184) {   // KKVsym tiles (cp = pair-pair 0..71)
            uint32_t hi, lo;
            split_pack(st[(2 * cp) * 72 + f], st[(2 * cp + 1) * 72 + f], hi, lo);
            const int ks = cp >> 3, kp8 = cp & 7;
            const int idx = tile_word(ks * 9 + nt, kp8 >> 2, row, kp8 & 3);
            sSt2[idx] = hi; sSt2[idx + 64] = lo;
        }
    }
    for (int w = tid; w < 648; w += 512) {
        const int kp = w / 72, f = w - kp * 72;
        float a, b;
        if (kp < 8) {
            a = st[ST_KV + (2 * kp) * 72 + f];
            b = st[ST_KV + (2 * kp + 1) * 72 + f];
        } else {   // row 16 = prefixed Vsum (col64 = token count), row 17 = 0
            a = st[ST_V + f];
            b = 0.f;
        }
        split_pack(a, b, sLh[w], sLl[w]);
    }
    __syncthreads();

    // SMSP-balanced tile assignment
    const int g = wid >> 2, s4 = wid & 3;
    const int tb = (g == 0) ? s4 : (g == 1) ? 7 - s4 : (g == 2) ? 8 + s4 : 15 - s4;
    const int rbase = tb * 16 + qr;

    float O[9][4];
#pragma unroll
    for (int nt = 0; nt < 9; nt++)
#pragma unroll
        for (int j = 0; j < 4; j++) O[nt][j] = 0.f;

    // ---- part 1: Wq_sym[t,p] = cw_p * q_d(p) * q_e(p)  @  KKVsym ----
    for (int ks = 0; ks < 9; ks++) {
        const int pA = ks * 16 + 2 * qc, pB = pA + 1, pC = pA + 8, pD = pA + 9;
        const int dA = cPT.d[pA], eA = cPT.e[pA]; const float wA = cPT.cw[pA];
        const int dB = cPT.d[pB], eB = cPT.e[pB]; const float wB = cPT.cw[pB];
        const int dC = cPT.d[pC], eC = cPT.e[pC]; const float wC = cPT.cw[pC];
        const int dD = cPT.d[pD], eD = cPT.e[pD]; const float wD = cPT.cw[pD];

        const float* qlo = sQ + rbase * 17;
        const float* qhi = qlo + 8 * 17;
        uint32_t Ah[4], Al[4];
        split_pack(wA * qlo[dA] * qlo[eA], wB * qlo[dB] * qlo[eB], Ah[0], Al[0]);
        split_pack(wA * qhi[dA] * qhi[eA], wB * qhi[dB] * qhi[eB], Ah[1], Al[1]);
        split_pack(wC * qlo[dC] * qlo[eC], wD * qlo[dD] * qlo[eD], Ah[2], Al[2]);
        split_pack(wC * qhi[dC] * qhi[eC], wD * qhi[dD] * qhi[eD], Ah[3], Al[3]);

#pragma unroll
        for (int nt = 0; nt < 9; nt++) {
            uint32_t bh0, bh1, bl0, bl1;
            ldsm_x4(bh0, bh1, bl0, bl1, tile_addr(sSt2s, ks * 9 + nt, lane));
            mma16816(O[nt], Ah, bh0, bh1);
            mma16816(O[nt], Ah, bl0, bl1);
            mma16816(O[nt], Al, bh0, bh1);
        }
    }

    // q A-fragments (linear part + S MMAs)
    uint32_t Aq_h[4], Aq_l[4];
    {
        const int rlo = rbase, rhi = rlo + 8;
        Aq_h[0] = sQh[rlo * 8 + qc];     Aq_l[0] = sQl[rlo * 8 + qc];
        Aq_h[1] = sQh[rhi * 8 + qc];     Aq_l[1] = sQl[rhi * 8 + qc];
        Aq_h[2] = sQh[rlo * 8 + qc + 4]; Aq_l[2] = sQl[rlo * 8 + qc + 4];
        Aq_h[3] = sQh[rhi * 8 + qc + 4]; Aq_l[3] = sQl[rhi * 8 + qc + 4];
    }

    // ---- part 2: linear (qhat @ KVext) + const row (Vsum_prev incl. count) ----
    {
        const int b0i = qc * 72 + qr, b1i = b0i + 288;
        const uint32_t onesA = (qc == 0) ? 0x00003F80u : 0u;   // bf16 1.0 low half
        const uint32_t Ac[4] = { onesA, onesA, 0u, 0u };
#pragma unroll
        for (int nt = 0; nt < 9; nt++) {
            const uint32_t bh0 = sLh[b0i + nt * 8], bh1 = sLh[b1i + nt * 8];
            const uint32_t bl0 = sLl[b0i + nt * 8], bl1 = sLl[b1i + nt * 8];
            const uint32_t cb_h = (qc == 0) ? sLh[576 + nt * 8 + qr] : 0u;
            const uint32_t cb_l = (qc == 0) ? sLl[576 + nt * 8 + qr] : 0u;
            mma16816(O[nt], Aq_h, bh0, bh1);
            mma16816(O[nt], Aq_h, bl0, bl1);
            mma16816(O[nt], Aq_l, bh0, bh1);
            mma16816(O[nt], Ac, cb_h, 0u);
            mma16816(O[nt], Ac, cb_l, 0u);
        }
    }

    // ---- part 3: intra-chunk causal A = tril(1+S+0.5S^2), fused ----
    {
        const int sulim = tb;
        for (int su = 0; su <= sulim; su++) {
            const int sbase = su * 16;
            float s0[4] = {0.f, 0.f, 0.f, 0.f};
            float s1[4] = {0.f, 0.f, 0.f, 0.f};
            {
                uint32_t kh0, kh1, kl0, kl1;
                ldsm_x4(kh0, kh1, kl0, kl1, tile_addr(sK2s, su * 2 + 0, lane));
                mma16816(s0, Aq_h, kh0, kh1);
                mma16816(s0, Aq_h, kl0, kl1);
                mma16816(s0, Aq_l, kh0, kh1);
            }
            {
                uint32_t kh0, kh1, kl0, kl1;
                ldsm_x4(kh0, kh1, kl0, kl1, tile_addr(sK2s, su * 2 + 1, lane));
                mma16816(s1, Aq_h, kh0, kh1);
                mma16816(s1, Aq_h, kl0, kl1);
                mma16816(s1, Aq_l, kh0, kh1);
            }

            const int rlo = rbase, rhi = rlo + 8;
            const int c0 = sbase + 2 * qc;
            float a00 = (c0     <= rlo) ? fmaf(0.5f * s0[0], s0[0], 1.f + s0[0]) : 0.f;
            float a01 = (c0 + 1 <= rlo) ? fmaf(0.5f * s0[1], s0[1], 1.f + s0[1]) : 0.f;
            float a10 = (c0     <= rhi) ? fmaf(0.5f * s0[2], s0[2], 1.f + s0[2]) : 0.f;
            float a11 = (c0 + 1 <= rhi) ? fmaf(0.5f * s0[3], s0[3], 1.f + s0[3]) : 0.f;
            float a20 = (c0 + 8 <= rlo) ? fmaf(0.5f * s1[0], s1[0], 1.f + s1[0]) : 0.f;
            float a21 = (c0 + 9 <= rlo) ? fmaf(0.5f * s1[1], s1[1], 1.f + s1[1]) : 0.f;
            float a30 = (c0 + 8 <= rhi) ? fmaf(0.5f * s1[2], s1[2], 1.f + s1[2]) : 0.f;
            float a31 = (c0 + 9 <= rhi) ? fmaf(0.5f * s1[3], s1[3], 1.f + s1[3]) : 0.f;

            uint32_t AH[4], AL[4];
            split_pack(a00, a01, AH[0], AL[0]);
            split_pack(a10, a11, AH[1], AL[1]);
            split_pack(a20, a21, AH[2], AL[2]);
            split_pack(a30, a31, AH[3], AL[3]);

#pragma unroll
            for (int nt = 0; nt < 9; nt++) {
                uint32_t bh0, bh1, bl0, bl1;
                ldsm_x4(bh0, bh1, bl0, bl1, tile_addr(sV2s, su * 9 + nt, lane));
                mma16816(O[nt], AH, bh0, bh1);
                mma16816(O[nt], AH, bl0, bl1);
                mma16816(O[nt], AL, bh0, bh1);
            }
        }
    }

    // ---- epilogue: z = col 64, divide, store ----
    {
        const float zlo = __shfl_sync(0xffffffffu, O[8][0], lane & 28);
        const float zhi = __shfl_sync(0xffffffffu, O[8][2], lane & 28);
        const float ilo = 1.f / (zlo + 1e-6f);
        const float ihi = 1.f / (zhi + 1e-6f);
        float* olo = out + ((size_t)bh * SEQ + (size_t)ch * CS + rbase) * DV;
        float* ohi = olo + 8 * DV;
#pragma unroll
        for (int nt = 0; nt < 8; nt++) {
            const int col = nt * 8 + 2 * qc;
            *(float2*)(olo + col) = make_float2(O[nt][0] * ilo, O[nt][1] * ilo);
            *(float2*)(ohi + col) = make_float2(O[nt][2] * ihi, O[nt][3] * ihi);
        }
    }
}

// ---------------------------------------------------------------------------
extern "C" void kernel_launch(void* const* d_in, const int* in_sizes, int n_in,
                              void* d_out, int out_size)
{
    const float* q = (const float*)d_in[0];
    const float* k = (const float*)d_in[1];
    const float* v = (const float*)d_in[2];
    float* out = (float*)d_out;

    const int smem1 = 17408 + 73728;                                      // 91136 B
    const int smem3 = (10368 + 18432 + 4096 + 2*2048 + 2*648 + 4352) * 4; // 170560 B
    cudaFuncSetAttribute(k1_sums,   cudaFuncAttributeMaxDynamicSharedMemorySize, smem1);
    cudaFuncSetAttribute(k3_output, cudaFuncAttributeMaxDynamicSharedMemorySize, smem3);

    dim3 grid(BH, NCH);
    k1_sums<<<grid, 288, smem1>>>(k, v);
    k2_prefix<<<dim3(BH, 12), 256>>>();
    k3_output<<<grid, 512, smem3>>>(q, k, v, out);
}